// round 1
// baseline (speedup 1.0000x reference)
#include <cuda_runtime.h>
#include <math.h>

#define BB    128
#define TT    256
#define INDIM 300
#define HH    512
#define NCLS  45
#define LNEPS 1e-5f

// ---------- device scratch (no allocation allowed) ----------
__device__ float g_W0[2 * INDIM * HH];        // folded emb->layer0 weight  [d][i][n]
__device__ float g_b0[2 * HH];                // folded bias                [d][n]
__device__ float g_X0[2 * TT * BB * HH];      // precomputed layer0 x-part [d][t][b][n]
__device__ float g_h [2 * 3 * BB * HH];       // current h per (d,layer)   [d][l][b][n]
__device__ float g_pp[8 * 2 * 3 * BB * HH];   // GEMM partials per k-chunk [c][d][l][b][n]
__device__ float g_o2[2 * TT * BB * HH];      // layer2 history            [d][t][b][n]

// ---------- zero the recurrent state ----------
__global__ void zero_h_kernel() {
    int i = blockIdx.x * blockDim.x + threadIdx.x;
    if (i < 2 * 3 * BB * HH) g_h[i] = 0.f;
}

// ---------- W0 = W_emb @ Wx0 ; b0 = b_emb @ Wx0 + bx0 ----------
// grid (8, 3, 2), block 256.  M = 301 (row 300 == b_emb), K = 512, N = 512
__global__ void w0_kernel(const float* __restrict__ W_emb, const float* __restrict__ b_emb,
                          const float* __restrict__ Wx_l2r, const float* __restrict__ bx_l2r,
                          const float* __restrict__ Wx_r2l, const float* __restrict__ bx_r2l) {
    const int d = blockIdx.z;
    const float* Wx0 = d ? Wx_r2l : Wx_l2r;   // layer 0 slice is at offset 0
    const float* bx0 = d ? bx_r2l : bx_l2r;
    const int n0 = blockIdx.x * 64;
    const int m0 = blockIdx.y * 128;
    __shared__ float As[16][136];
    __shared__ float Bs[16][64];
    const int tid = threadIdx.x;
    const int ty = tid >> 4, tx = tid & 15;
    float acc[8][4];
#pragma unroll
    for (int i = 0; i < 8; i++)
#pragma unroll
        for (int j = 0; j < 4; j++) acc[i][j] = 0.f;

    for (int k0 = 0; k0 < HH; k0 += 16) {
        {
            const int row = tid >> 2, c4 = (tid & 3) * 4;
#pragma unroll
            for (int rr = 0; rr < 2; rr++) {
                int r = row + rr * 64;
                int gm = m0 + r;
                float4 av = make_float4(0.f, 0.f, 0.f, 0.f);
                if (gm < INDIM)       av = *(const float4*)(W_emb + (size_t)gm * HH + k0 + c4);
                else if (gm == INDIM) av = *(const float4*)(b_emb + k0 + c4);
                As[c4 + 0][r] = av.x; As[c4 + 1][r] = av.y;
                As[c4 + 2][r] = av.z; As[c4 + 3][r] = av.w;
            }
        }
        {
            const int row = tid >> 4, c4 = (tid & 15) * 4;
            float4 bv = *(const float4*)(Wx0 + (size_t)(k0 + row) * HH + n0 + c4);
            *(float4*)(&Bs[row][c4]) = bv;
        }
        __syncthreads();
#pragma unroll
        for (int kk = 0; kk < 16; kk++) {
            float4 a0 = *(const float4*)(&As[kk][ty * 8]);
            float4 a1 = *(const float4*)(&As[kk][ty * 8 + 4]);
            float4 b4 = *(const float4*)(&Bs[kk][tx * 4]);
            float a[8] = {a0.x, a0.y, a0.z, a0.w, a1.x, a1.y, a1.z, a1.w};
            float b[4] = {b4.x, b4.y, b4.z, b4.w};
#pragma unroll
            for (int i = 0; i < 8; i++)
#pragma unroll
                for (int j = 0; j < 4; j++) acc[i][j] = fmaf(a[i], b[j], acc[i][j]);
        }
        __syncthreads();
    }
#pragma unroll
    for (int i = 0; i < 8; i++) {
        int gm = m0 + ty * 8 + i;
        int gn = n0 + tx * 4;
        if (gm < INDIM) {
#pragma unroll
            for (int j = 0; j < 4; j++) g_W0[(size_t)(d * INDIM + gm) * HH + gn + j] = acc[i][j];
        } else if (gm == INDIM) {
#pragma unroll
            for (int j = 0; j < 4; j++) g_b0[d * HH + gn + j] = acc[i][j] + bx0[gn + j];
        }
    }
}

// ---------- X0 = x @ W0 + b0  (per direction) ----------
// grid (8, 256, 2), block 256.  M = 32768 rows (b*T+t), K = 300, N = 512
__global__ void x0_kernel(const float* __restrict__ x, const float* __restrict__ rx) {
    const int d = blockIdx.z;
    const float* A  = d ? rx : x;
    const float* Bw = g_W0 + (size_t)d * INDIM * HH;
    const int n0 = blockIdx.x * 64;
    const int m0 = blockIdx.y * 128;
    __shared__ float As[16][136];
    __shared__ float Bs[16][64];
    const int tid = threadIdx.x;
    const int ty = tid >> 4, tx = tid & 15;
    float acc[8][4];
#pragma unroll
    for (int i = 0; i < 8; i++)
#pragma unroll
        for (int j = 0; j < 4; j++) acc[i][j] = 0.f;

    for (int k0 = 0; k0 < INDIM; k0 += 16) {
        const bool full = (k0 + 16) <= INDIM;
        {
            const int row = tid >> 2, c4 = (tid & 3) * 4;
#pragma unroll
            for (int rr = 0; rr < 2; rr++) {
                int r = row + rr * 64;
                size_t gm = (size_t)(m0 + r);
                float4 av;
                if (full) {
                    av = *(const float4*)(A + gm * INDIM + k0 + c4);
                } else {
                    av.x = (k0 + c4 + 0 < INDIM) ? A[gm * INDIM + k0 + c4 + 0] : 0.f;
                    av.y = (k0 + c4 + 1 < INDIM) ? A[gm * INDIM + k0 + c4 + 1] : 0.f;
                    av.z = (k0 + c4 + 2 < INDIM) ? A[gm * INDIM + k0 + c4 + 2] : 0.f;
                    av.w = (k0 + c4 + 3 < INDIM) ? A[gm * INDIM + k0 + c4 + 3] : 0.f;
                }
                As[c4 + 0][r] = av.x; As[c4 + 1][r] = av.y;
                As[c4 + 2][r] = av.z; As[c4 + 3][r] = av.w;
            }
        }
        {
            const int row = tid >> 4, c4 = (tid & 15) * 4;
            float4 bv = make_float4(0.f, 0.f, 0.f, 0.f);
            if (k0 + row < INDIM) bv = *(const float4*)(Bw + (size_t)(k0 + row) * HH + n0 + c4);
            *(float4*)(&Bs[row][c4]) = bv;
        }
        __syncthreads();
#pragma unroll
        for (int kk = 0; kk < 16; kk++) {
            float4 a0 = *(const float4*)(&As[kk][ty * 8]);
            float4 a1 = *(const float4*)(&As[kk][ty * 8 + 4]);
            float4 b4 = *(const float4*)(&Bs[kk][tx * 4]);
            float a[8] = {a0.x, a0.y, a0.z, a0.w, a1.x, a1.y, a1.z, a1.w};
            float b[4] = {b4.x, b4.y, b4.z, b4.w};
#pragma unroll
            for (int i = 0; i < 8; i++)
#pragma unroll
                for (int j = 0; j < 4; j++) acc[i][j] = fmaf(a[i], b[j], acc[i][j]);
        }
        __syncthreads();
    }
#pragma unroll
    for (int i = 0; i < 8; i++) {
        int gm = m0 + ty * 8 + i;
        int bidx = gm >> 8;            // T = 256
        int t    = gm & 255;
        int gn = n0 + tx * 4;
        size_t base = ((size_t)(d * TT + t) * BB + bidx) * HH + gn;
#pragma unroll
        for (int j = 0; j < 4; j++) g_X0[base + j] = acc[i][j] + g_b0[d * HH + gn + j];
    }
}

// ---------- per-wavefront-step GEMM: partial pre-activations ----------
// grid (16, 8, 6), block 128.  Each CTA: 128x32 tile over a 128-wide K chunk.
__global__ void step_kernel(int s,
                            const float* __restrict__ Wx_l2r, const float* __restrict__ Wh_l2r,
                            const float* __restrict__ Wx_r2l, const float* __restrict__ Wh_r2l) {
    const int task = blockIdx.z;
    const int d = task / 3;
    const int l = task - d * 3;
    const int t = s - l;
    if (t < 0 || t >= TT) return;
    const int chunk = blockIdx.y;
    const float* Wxd = d ? Wx_r2l : Wx_l2r;
    const float* Whd = d ? Wh_r2l : Wh_l2r;
    const float* Ablk;
    const float* W;
    int koff;
    if (l == 0) {
        if (chunk >= 4) return;
        Ablk = g_h + (size_t)(d * 3 + 0) * BB * HH;
        W = Whd;                       // layer 0 slice at offset 0
        koff = chunk * 128;
    } else if (chunk < 4) {
        Ablk = g_h + (size_t)(d * 3 + l - 1) * BB * HH;
        W = Wxd + (size_t)l * HH * HH;
        koff = chunk * 128;
    } else {
        Ablk = g_h + (size_t)(d * 3 + l) * BB * HH;
        W = Whd + (size_t)l * HH * HH;
        koff = (chunk - 4) * 128;
    }
    const int n0 = blockIdx.x * 32;
    __shared__ float As[16][136];
    __shared__ float Bs[16][32];
    const int tid = threadIdx.x;
    const int ty = tid >> 3, tx = tid & 7;
    float acc[8][4];
#pragma unroll
    for (int i = 0; i < 8; i++)
#pragma unroll
        for (int j = 0; j < 4; j++) acc[i][j] = 0.f;

    for (int k0 = 0; k0 < 128; k0 += 16) {
        {
            const int row = tid >> 2, c4 = (tid & 3) * 4;
#pragma unroll
            for (int rr = 0; rr < 4; rr++) {
                int r = row + rr * 32;
                float4 av = *(const float4*)(Ablk + (size_t)r * HH + koff + k0 + c4);
                As[c4 + 0][r] = av.x; As[c4 + 1][r] = av.y;
                As[c4 + 2][r] = av.z; As[c4 + 3][r] = av.w;
            }
        }
        {
            const int row = tid >> 3, c4 = (tid & 7) * 4;
            float4 bv = *(const float4*)(W + (size_t)(koff + k0 + row) * HH + n0 + c4);
            *(float4*)(&Bs[row][c4]) = bv;
        }
        __syncthreads();
#pragma unroll
        for (int kk = 0; kk < 16; kk++) {
            float4 a0 = *(const float4*)(&As[kk][ty * 8]);
            float4 a1 = *(const float4*)(&As[kk][ty * 8 + 4]);
            float4 b4 = *(const float4*)(&Bs[kk][tx * 4]);
            float a[8] = {a0.x, a0.y, a0.z, a0.w, a1.x, a1.y, a1.z, a1.w};
            float b[4] = {b4.x, b4.y, b4.z, b4.w};
#pragma unroll
            for (int i = 0; i < 8; i++)
#pragma unroll
                for (int j = 0; j < 4; j++) acc[i][j] = fmaf(a[i], b[j], acc[i][j]);
        }
        __syncthreads();
    }
    float* out = g_pp + (size_t)((chunk * 2 + d) * 3 + l) * BB * HH;
#pragma unroll
    for (int i = 0; i < 8; i++) {
        *(float4*)(out + (size_t)(ty * 8 + i) * HH + n0 + tx * 4) =
            make_float4(acc[i][0], acc[i][1], acc[i][2], acc[i][3]);
    }
}

// ---------- per-step LayerNorm + tanh ----------
// grid (128, 6), block 256. One block per (batch row, task).
__global__ void ln_kernel(int s,
                          const float* __restrict__ bx_l2r, const float* __restrict__ bh_l2r,
                          const float* __restrict__ bx_r2l, const float* __restrict__ bh_r2l,
                          const float* __restrict__ ln_g,  const float* __restrict__ ln_b) {
    const int task = blockIdx.y;
    const int d = task / 3;
    const int l = task - d * 3;
    const int t = s - l;
    if (t < 0 || t >= TT) return;
    const int b = blockIdx.x;
    const float* bx = (d ? bx_r2l : bx_l2r) + l * HH;
    const float* bh = (d ? bh_r2l : bh_l2r) + l * HH;
    const int nch = (l == 0) ? 4 : 8;
    const int tid = threadIdx.x;

    float v[2];
    float s1 = 0.f, s2 = 0.f;
#pragma unroll
    for (int e = 0; e < 2; e++) {
        int j = tid + e * 256;
        float val = bh[j];
        if (l == 0) val += g_X0[((size_t)(d * TT + t) * BB + b) * HH + j];
        else        val += bx[j];
        for (int c = 0; c < nch; c++)
            val += g_pp[(size_t)((c * 2 + d) * 3 + l) * BB * HH + (size_t)b * HH + j];
        v[e] = val;
        s1 += val;
        s2 += val * val;
    }
    __shared__ float r1[256], r2[256];
    r1[tid] = s1; r2[tid] = s2;
    __syncthreads();
    for (int off = 128; off > 0; off >>= 1) {
        if (tid < off) { r1[tid] += r1[tid + off]; r2[tid] += r2[tid + off]; }
        __syncthreads();
    }
    const float mean = r1[0] * (1.f / HH);
    const float var  = r2[0] * (1.f / HH) - mean * mean;
    const float inv  = rsqrtf(var + LNEPS);
#pragma unroll
    for (int e = 0; e < 2; e++) {
        int j = tid + e * 256;
        float hn = tanhf((v[e] - mean) * inv * ln_g[l * HH + j] + ln_b[l * HH + j]);
        g_h[(size_t)(d * 3 + l) * BB * HH + (size_t)b * HH + j] = hn;
        if (l == 2) g_o2[((size_t)(d * TT + t) * BB + b) * HH + j] = hn;
    }
}

// ---------- gather + concat + FC ----------
// grid (8192), block 256: 4 output rows per block, 64 threads per row.
__global__ void final_kernel(const int* __restrict__ pad,
                             const float* __restrict__ W_fc, const float* __restrict__ b_fc,
                             float* __restrict__ out) {
    __shared__ float cs[4][1024];
    const int sub  = threadIdx.x >> 6;
    const int lane = threadIdx.x & 63;
    const int r = blockIdx.x * 4 + sub;
    const int b = r >> 8;        // T = 256
    const int t = r & 255;
    const int p = pad[b];
    const int tt = (t < p) ? (p - t - 1) : t;
    const float* a0 = g_o2 + ((size_t)(0 * TT + t)  * BB + b) * HH;
    const float* a1 = g_o2 + ((size_t)(1 * TT + tt) * BB + b) * HH;
#pragma unroll
    for (int i = 0; i < 4; i++) {
        int j = lane * 4 + i * 256;
        float4 vv = (j < 512) ? *(const float4*)(a0 + j) : *(const float4*)(a1 + j - 512);
        *(float4*)(&cs[sub][j]) = vv;
    }
    __syncthreads();
    if (lane < NCLS) {
        float acc = b_fc[lane];
#pragma unroll 8
        for (int k = 0; k < 1024; k++) acc = fmaf(cs[sub][k], W_fc[k * NCLS + lane], acc);
        out[(size_t)r * NCLS + lane] = acc;
    }
}

// ---------- host launcher ----------
extern "C" void kernel_launch(void* const* d_in, const int* in_sizes, int n_in,
                              void* d_out, int out_size) {
    (void)in_sizes; (void)n_in; (void)out_size;
    const float* x      = (const float*)d_in[0];
    const float* rx     = (const float*)d_in[1];
    const int*   pad    = (const int*)  d_in[2];
    // d_in[3] = max_length (always 256 for this shape)
    const float* W_emb  = (const float*)d_in[4];
    const float* b_emb  = (const float*)d_in[5];
    const float* Wx_l2r = (const float*)d_in[6];
    const float* bx_l2r = (const float*)d_in[7];
    const float* Wh_l2r = (const float*)d_in[8];
    const float* bh_l2r = (const float*)d_in[9];
    const float* Wx_r2l = (const float*)d_in[10];
    const float* bx_r2l = (const float*)d_in[11];
    const float* Wh_r2l = (const float*)d_in[12];
    const float* bh_r2l = (const float*)d_in[13];
    const float* ln_g   = (const float*)d_in[14];
    const float* ln_b   = (const float*)d_in[15];
    const float* W_fc   = (const float*)d_in[16];
    const float* b_fc   = (const float*)d_in[17];
    float* out = (float*)d_out;

    zero_h_kernel<<<(2 * 3 * BB * HH + 255) / 256, 256>>>();
    w0_kernel<<<dim3(8, 3, 2), 256>>>(W_emb, b_emb, Wx_l2r, bx_l2r, Wx_r2l, bx_r2l);
    x0_kernel<<<dim3(8, 256, 2), 256>>>(x, rx);

    for (int s = 0; s < TT + 2; s++) {
        step_kernel<<<dim3(16, 8, 6), 128>>>(s, Wx_l2r, Wh_l2r, Wx_r2l, Wh_r2l);
        ln_kernel<<<dim3(128, 6), 256>>>(s, bx_l2r, bh_l2r, bx_r2l, bh_r2l, ln_g, ln_b);
    }

    final_kernel<<<8192, 256>>>(pad, W_fc, b_fc, out);
}

// round 2
// speedup vs baseline: 1.0013x; 1.0013x over previous
#include <cuda_runtime.h>
#include <math.h>

#define BB    128
#define TT    256
#define INDIM 300
#define HH    512
#define NCLS  45
#define LNEPS 1e-5f

// ---------- device scratch (no allocation allowed) ----------
__device__ float g_W0[2 * INDIM * HH];        // folded emb->layer0 weight  [d][i][n]
__device__ float g_b0[2 * HH];                // folded bias                [d][n]
__device__ float g_X0[2 * TT * BB * HH];      // precomputed layer0 x-part [d][t][b][n]
__device__ float g_h [2 * 3 * BB * HH];       // current h per (d,layer)   [d][l][b][n]
__device__ float g_pp[8 * 2 * 3 * BB * HH];   // GEMM partials per k-chunk [c][d][l][b][n]
__device__ float g_o2[2 * TT * BB * HH];      // layer2 history            [d][t][b][n]

// ---------- zero the recurrent state ----------
__global__ void zero_h_kernel() {
    int i = blockIdx.x * blockDim.x + threadIdx.x;
    if (i < 2 * 3 * BB * HH) g_h[i] = 0.f;
}

// ---------- W0 = W_emb @ Wx0 ; b0 = b_emb @ Wx0 + bx0 ----------
// grid (8, 3, 2), block 256.  M = 301 (row 300 == b_emb), K = 512, N = 512
__global__ void w0_kernel(const float* __restrict__ W_emb, const float* __restrict__ b_emb,
                          const float* __restrict__ Wx_l2r, const float* __restrict__ bx_l2r,
                          const float* __restrict__ Wx_r2l, const float* __restrict__ bx_r2l) {
    const int d = blockIdx.z;
    const float* Wx0 = d ? Wx_r2l : Wx_l2r;   // layer 0 slice is at offset 0
    const float* bx0 = d ? bx_r2l : bx_l2r;
    const int n0 = blockIdx.x * 64;
    const int m0 = blockIdx.y * 128;
    __shared__ float As[16][136];
    __shared__ float Bs[16][64];
    const int tid = threadIdx.x;
    const int ty = tid >> 4, tx = tid & 15;
    float acc[8][4];
#pragma unroll
    for (int i = 0; i < 8; i++)
#pragma unroll
        for (int j = 0; j < 4; j++) acc[i][j] = 0.f;

    for (int k0 = 0; k0 < HH; k0 += 16) {
        {
            const int row = tid >> 2, c4 = (tid & 3) * 4;
#pragma unroll
            for (int rr = 0; rr < 2; rr++) {
                int r = row + rr * 64;
                int gm = m0 + r;
                float4 av = make_float4(0.f, 0.f, 0.f, 0.f);
                if (gm < INDIM)       av = *(const float4*)(W_emb + (size_t)gm * HH + k0 + c4);
                else if (gm == INDIM) av = *(const float4*)(b_emb + k0 + c4);
                As[c4 + 0][r] = av.x; As[c4 + 1][r] = av.y;
                As[c4 + 2][r] = av.z; As[c4 + 3][r] = av.w;
            }
        }
        {
            const int row = tid >> 4, c4 = (tid & 15) * 4;
            float4 bv = *(const float4*)(Wx0 + (size_t)(k0 + row) * HH + n0 + c4);
            *(float4*)(&Bs[row][c4]) = bv;
        }
        __syncthreads();
#pragma unroll
        for (int kk = 0; kk < 16; kk++) {
            float4 a0 = *(const float4*)(&As[kk][ty * 8]);
            float4 a1 = *(const float4*)(&As[kk][ty * 8 + 4]);
            float4 b4 = *(const float4*)(&Bs[kk][tx * 4]);
            float a[8] = {a0.x, a0.y, a0.z, a0.w, a1.x, a1.y, a1.z, a1.w};
            float b[4] = {b4.x, b4.y, b4.z, b4.w};
#pragma unroll
            for (int i = 0; i < 8; i++)
#pragma unroll
                for (int j = 0; j < 4; j++) acc[i][j] = fmaf(a[i], b[j], acc[i][j]);
        }
        __syncthreads();
    }
#pragma unroll
    for (int i = 0; i < 8; i++) {
        int gm = m0 + ty * 8 + i;
        int gn = n0 + tx * 4;
        if (gm < INDIM) {
#pragma unroll
            for (int j = 0; j < 4; j++) g_W0[(size_t)(d * INDIM + gm) * HH + gn + j] = acc[i][j];
        } else if (gm == INDIM) {
#pragma unroll
            for (int j = 0; j < 4; j++) g_b0[d * HH + gn + j] = acc[i][j] + bx0[gn + j];
        }
    }
}

// ---------- X0 = x @ W0 + b0  (per direction) ----------
// grid (8, 256, 2), block 256.  M = 32768 rows (b*T+t), K = 300, N = 512
__global__ void x0_kernel(const float* __restrict__ x, const float* __restrict__ rx) {
    const int d = blockIdx.z;
    const float* A  = d ? rx : x;
    const float* Bw = g_W0 + (size_t)d * INDIM * HH;
    const int n0 = blockIdx.x * 64;
    const int m0 = blockIdx.y * 128;
    __shared__ float As[16][136];
    __shared__ float Bs[16][64];
    const int tid = threadIdx.x;
    const int ty = tid >> 4, tx = tid & 15;
    float acc[8][4];
#pragma unroll
    for (int i = 0; i < 8; i++)
#pragma unroll
        for (int j = 0; j < 4; j++) acc[i][j] = 0.f;

    for (int k0 = 0; k0 < INDIM; k0 += 16) {
        const bool full = (k0 + 16) <= INDIM;
        {
            const int row = tid >> 2, c4 = (tid & 3) * 4;
#pragma unroll
            for (int rr = 0; rr < 2; rr++) {
                int r = row + rr * 64;
                size_t gm = (size_t)(m0 + r);
                float4 av;
                if (full) {
                    av = *(const float4*)(A + gm * INDIM + k0 + c4);
                } else {
                    av.x = (k0 + c4 + 0 < INDIM) ? A[gm * INDIM + k0 + c4 + 0] : 0.f;
                    av.y = (k0 + c4 + 1 < INDIM) ? A[gm * INDIM + k0 + c4 + 1] : 0.f;
                    av.z = (k0 + c4 + 2 < INDIM) ? A[gm * INDIM + k0 + c4 + 2] : 0.f;
                    av.w = (k0 + c4 + 3 < INDIM) ? A[gm * INDIM + k0 + c4 + 3] : 0.f;
                }
                As[c4 + 0][r] = av.x; As[c4 + 1][r] = av.y;
                As[c4 + 2][r] = av.z; As[c4 + 3][r] = av.w;
            }
        }
        {
            const int row = tid >> 4, c4 = (tid & 15) * 4;
            float4 bv = make_float4(0.f, 0.f, 0.f, 0.f);
            if (k0 + row < INDIM) bv = *(const float4*)(Bw + (size_t)(k0 + row) * HH + n0 + c4);
            *(float4*)(&Bs[row][c4]) = bv;
        }
        __syncthreads();
#pragma unroll
        for (int kk = 0; kk < 16; kk++) {
            float4 a0 = *(const float4*)(&As[kk][ty * 8]);
            float4 a1 = *(const float4*)(&As[kk][ty * 8 + 4]);
            float4 b4 = *(const float4*)(&Bs[kk][tx * 4]);
            float a[8] = {a0.x, a0.y, a0.z, a0.w, a1.x, a1.y, a1.z, a1.w};
            float b[4] = {b4.x, b4.y, b4.z, b4.w};
#pragma unroll
            for (int i = 0; i < 8; i++)
#pragma unroll
                for (int j = 0; j < 4; j++) acc[i][j] = fmaf(a[i], b[j], acc[i][j]);
        }
        __syncthreads();
    }
#pragma unroll
    for (int i = 0; i < 8; i++) {
        int gm = m0 + ty * 8 + i;
        int bidx = gm >> 8;            // T = 256
        int t    = gm & 255;
        int gn = n0 + tx * 4;
        size_t base = ((size_t)(d * TT + t) * BB + bidx) * HH + gn;
#pragma unroll
        for (int j = 0; j < 4; j++) g_X0[base + j] = acc[i][j] + g_b0[d * HH + gn + j];
    }
}

// ---------- per-wavefront-step GEMM: partial pre-activations ----------
// grid (16, 8, 6), block 128.  Each CTA: 128x32 tile over a 128-wide K chunk.
__global__ void step_kernel(int s,
                            const float* __restrict__ Wx_l2r, const float* __restrict__ Wh_l2r,
                            const float* __restrict__ Wx_r2l, const float* __restrict__ Wh_r2l) {
    const int task = blockIdx.z;
    const int d = task / 3;
    const int l = task - d * 3;
    const int t = s - l;
    if (t < 0 || t >= TT) return;
    const int chunk = blockIdx.y;
    const float* Wxd = d ? Wx_r2l : Wx_l2r;
    const float* Whd = d ? Wh_r2l : Wh_l2r;
    const float* Ablk;
    const float* W;
    int koff;
    if (l == 0) {
        if (chunk >= 4) return;
        Ablk = g_h + (size_t)(d * 3 + 0) * BB * HH;
        W = Whd;                       // layer 0 slice at offset 0
        koff = chunk * 128;
    } else if (chunk < 4) {
        Ablk = g_h + (size_t)(d * 3 + l - 1) * BB * HH;
        W = Wxd + (size_t)l * HH * HH;
        koff = chunk * 128;
    } else {
        Ablk = g_h + (size_t)(d * 3 + l) * BB * HH;
        W = Whd + (size_t)l * HH * HH;
        koff = (chunk - 4) * 128;
    }
    const int n0 = blockIdx.x * 32;
    __shared__ float As[16][136];
    __shared__ float Bs[16][32];
    const int tid = threadIdx.x;
    const int ty = tid >> 3, tx = tid & 7;
    float acc[8][4];
#pragma unroll
    for (int i = 0; i < 8; i++)
#pragma unroll
        for (int j = 0; j < 4; j++) acc[i][j] = 0.f;

    for (int k0 = 0; k0 < 128; k0 += 16) {
        {
            const int row = tid >> 2, c4 = (tid & 3) * 4;
#pragma unroll
            for (int rr = 0; rr < 4; rr++) {
                int r = row + rr * 32;
                float4 av = *(const float4*)(Ablk + (size_t)r * HH + koff + k0 + c4);
                As[c4 + 0][r] = av.x; As[c4 + 1][r] = av.y;
                As[c4 + 2][r] = av.z; As[c4 + 3][r] = av.w;
            }
        }
        {
            const int row = tid >> 3, c4 = (tid & 7) * 4;
            float4 bv = *(const float4*)(W + (size_t)(koff + k0 + row) * HH + n0 + c4);
            *(float4*)(&Bs[row][c4]) = bv;
        }
        __syncthreads();
#pragma unroll
        for (int kk = 0; kk < 16; kk++) {
            float4 a0 = *(const float4*)(&As[kk][ty * 8]);
            float4 a1 = *(const float4*)(&As[kk][ty * 8 + 4]);
            float4 b4 = *(const float4*)(&Bs[kk][tx * 4]);
            float a[8] = {a0.x, a0.y, a0.z, a0.w, a1.x, a1.y, a1.z, a1.w};
            float b[4] = {b4.x, b4.y, b4.z, b4.w};
#pragma unroll
            for (int i = 0; i < 8; i++)
#pragma unroll
                for (int j = 0; j < 4; j++) acc[i][j] = fmaf(a[i], b[j], acc[i][j]);
        }
        __syncthreads();
    }
    float* out = g_pp + (size_t)((chunk * 2 + d) * 3 + l) * BB * HH;
#pragma unroll
    for (int i = 0; i < 8; i++) {
        *(float4*)(out + (size_t)(ty * 8 + i) * HH + n0 + tx * 4) =
            make_float4(acc[i][0], acc[i][1], acc[i][2], acc[i][3]);
    }
}

// ---------- per-step LayerNorm + tanh ----------
// grid (128, 6), block 256. One block per (batch row, task).
__global__ void ln_kernel(int s,
                          const float* __restrict__ bx_l2r, const float* __restrict__ bh_l2r,
                          const float* __restrict__ bx_r2l, const float* __restrict__ bh_r2l,
                          const float* __restrict__ ln_g,  const float* __restrict__ ln_b) {
    const int task = blockIdx.y;
    const int d = task / 3;
    const int l = task - d * 3;
    const int t = s - l;
    if (t < 0 || t >= TT) return;
    const int b = blockIdx.x;
    const float* bx = (d ? bx_r2l : bx_l2r) + l * HH;
    const float* bh = (d ? bh_r2l : bh_l2r) + l * HH;
    const int nch = (l == 0) ? 4 : 8;
    const int tid = threadIdx.x;

    float v[2];
    float s1 = 0.f, s2 = 0.f;
#pragma unroll
    for (int e = 0; e < 2; e++) {
        int j = tid + e * 256;
        float val = bh[j];
        if (l == 0) val += g_X0[((size_t)(d * TT + t) * BB + b) * HH + j];
        else        val += bx[j];
        for (int c = 0; c < nch; c++)
            val += g_pp[(size_t)((c * 2 + d) * 3 + l) * BB * HH + (size_t)b * HH + j];
        v[e] = val;
        s1 += val;
        s2 += val * val;
    }
    __shared__ float r1[256], r2[256];
    r1[tid] = s1; r2[tid] = s2;
    __syncthreads();
    for (int off = 128; off > 0; off >>= 1) {
        if (tid < off) { r1[tid] += r1[tid + off]; r2[tid] += r2[tid + off]; }
        __syncthreads();
    }
    const float mean = r1[0] * (1.f / HH);
    const float var  = r2[0] * (1.f / HH) - mean * mean;
    const float inv  = rsqrtf(var + LNEPS);
#pragma unroll
    for (int e = 0; e < 2; e++) {
        int j = tid + e * 256;
        float hn = tanhf((v[e] - mean) * inv * ln_g[l * HH + j] + ln_b[l * HH + j]);
        g_h[(size_t)(d * 3 + l) * BB * HH + (size_t)b * HH + j] = hn;
        if (l == 2) g_o2[((size_t)(d * TT + t) * BB + b) * HH + j] = hn;
    }
}

// ---------- gather + concat + FC ----------
// grid (8192), block 256: 4 output rows per block, 64 threads per row.
__global__ void final_kernel(const int* __restrict__ pad,
                             const float* __restrict__ W_fc, const float* __restrict__ b_fc,
                             float* __restrict__ out) {
    __shared__ float cs[4][1024];
    const int sub  = threadIdx.x >> 6;
    const int lane = threadIdx.x & 63;
    const int r = blockIdx.x * 4 + sub;
    const int b = r >> 8;        // T = 256
    const int t = r & 255;
    const int p = pad[b];
    const int tt = (t < p) ? (p - t - 1) : t;
    const float* a0 = g_o2 + ((size_t)(0 * TT + t)  * BB + b) * HH;
    const float* a1 = g_o2 + ((size_t)(1 * TT + tt) * BB + b) * HH;
#pragma unroll
    for (int i = 0; i < 4; i++) {
        int j = lane * 4 + i * 256;
        float4 vv = (j < 512) ? *(const float4*)(a0 + j) : *(const float4*)(a1 + j - 512);
        *(float4*)(&cs[sub][j]) = vv;
    }
    __syncthreads();
    if (lane < NCLS) {
        float acc = b_fc[lane];
#pragma unroll 8
        for (int k = 0; k < 1024; k++) acc = fmaf(cs[sub][k], W_fc[k * NCLS + lane], acc);
        out[(size_t)r * NCLS + lane] = acc;
    }
}

// ---------- host launcher ----------
extern "C" void kernel_launch(void* const* d_in, const int* in_sizes, int n_in,
                              void* d_out, int out_size) {
    (void)in_sizes; (void)n_in; (void)out_size;
    const float* x      = (const float*)d_in[0];
    const float* rx     = (const float*)d_in[1];
    const int*   pad    = (const int*)  d_in[2];
    // d_in[3] = max_length (always 256 for this shape)
    const float* W_emb  = (const float*)d_in[4];
    const float* b_emb  = (const float*)d_in[5];
    const float* Wx_l2r = (const float*)d_in[6];
    const float* bx_l2r = (const float*)d_in[7];
    const float* Wh_l2r = (const float*)d_in[8];
    const float* bh_l2r = (const float*)d_in[9];
    const float* Wx_r2l = (const float*)d_in[10];
    const float* bx_r2l = (const float*)d_in[11];
    const float* Wh_r2l = (const float*)d_in[12];
    const float* bh_r2l = (const float*)d_in[13];
    const float* ln_g   = (const float*)d_in[14];
    const float* ln_b   = (const float*)d_in[15];
    const float* W_fc   = (const float*)d_in[16];
    const float* b_fc   = (const float*)d_in[17];
    float* out = (float*)d_out;

    zero_h_kernel<<<(2 * 3 * BB * HH + 255) / 256, 256>>>();
    w0_kernel<<<dim3(8, 3, 2), 256>>>(W_emb, b_emb, Wx_l2r, bx_l2r, Wx_r2l, bx_r2l);
    x0_kernel<<<dim3(8, 256, 2), 256>>>(x, rx);

    for (int s = 0; s < TT + 2; s++) {
        step_kernel<<<dim3(16, 8, 6), 128>>>(s, Wx_l2r, Wh_l2r, Wx_r2l, Wh_r2l);
        ln_kernel<<<dim3(128, 6), 256>>>(s, bx_l2r, bh_l2r, bx_r2l, bh_r2l, ln_g, ln_b);
    }

    final_kernel<<<8192, 256>>>(pad, W_fc, b_fc, out);
}

// round 3
// speedup vs baseline: 1.0041x; 1.0028x over previous
#include <cuda_runtime.h>
#include <math.h>

#define BB    128
#define TT    256
#define INDIM 300
#define HH    512
#define NCLS  45
#define LNEPS 1e-5f

// ---------- device scratch (no allocation allowed) ----------
__device__ float g_W0[2 * INDIM * HH];        // folded emb->layer0 weight  [d][i][n]
__device__ float g_b0[2 * HH];                // folded bias                [d][n]
__device__ float g_X0[2 * TT * BB * HH];      // precomputed layer0 x-part [d][t][b][n]
__device__ float g_h [2 * 3 * BB * HH];       // current h per (d,layer)   [d][l][b][n]
__device__ float g_pp[8 * 2 * 3 * BB * HH];   // GEMM partials per k-chunk [c][d][l][b][n]
__device__ float g_o2[2 * TT * BB * HH];      // layer2 history            [d][t][b][n]

// ---------- zero the recurrent state ----------
__global__ void zero_h_kernel() {
    int i = blockIdx.x * blockDim.x + threadIdx.x;
    if (i < 2 * 3 * BB * HH) g_h[i] = 0.f;
}

// ---------- W0 = W_emb @ Wx0 ; b0 = b_emb @ Wx0 + bx0 ----------
// grid (8, 3, 2), block 256.  M = 301 (row 300 == b_emb), K = 512, N = 512
__global__ void w0_kernel(const float* __restrict__ W_emb, const float* __restrict__ b_emb,
                          const float* __restrict__ Wx_l2r, const float* __restrict__ bx_l2r,
                          const float* __restrict__ Wx_r2l, const float* __restrict__ bx_r2l) {
    const int d = blockIdx.z;
    const float* Wx0 = d ? Wx_r2l : Wx_l2r;   // layer 0 slice is at offset 0
    const float* bx0 = d ? bx_r2l : bx_l2r;
    const int n0 = blockIdx.x * 64;
    const int m0 = blockIdx.y * 128;
    __shared__ float As[16][136];
    __shared__ float Bs[16][64];
    const int tid = threadIdx.x;
    const int ty = tid >> 4, tx = tid & 15;
    float acc[8][4];
#pragma unroll
    for (int i = 0; i < 8; i++)
#pragma unroll
        for (int j = 0; j < 4; j++) acc[i][j] = 0.f;

    for (int k0 = 0; k0 < HH; k0 += 16) {
        {
            const int row = tid >> 2, c4 = (tid & 3) * 4;
#pragma unroll
            for (int rr = 0; rr < 2; rr++) {
                int r = row + rr * 64;
                int gm = m0 + r;
                float4 av = make_float4(0.f, 0.f, 0.f, 0.f);
                if (gm < INDIM)       av = *(const float4*)(W_emb + (size_t)gm * HH + k0 + c4);
                else if (gm == INDIM) av = *(const float4*)(b_emb + k0 + c4);
                As[c4 + 0][r] = av.x; As[c4 + 1][r] = av.y;
                As[c4 + 2][r] = av.z; As[c4 + 3][r] = av.w;
            }
        }
        {
            const int row = tid >> 4, c4 = (tid & 15) * 4;
            float4 bv = *(const float4*)(Wx0 + (size_t)(k0 + row) * HH + n0 + c4);
            *(float4*)(&Bs[row][c4]) = bv;
        }
        __syncthreads();
#pragma unroll
        for (int kk = 0; kk < 16; kk++) {
            float4 a0 = *(const float4*)(&As[kk][ty * 8]);
            float4 a1 = *(const float4*)(&As[kk][ty * 8 + 4]);
            float4 b4 = *(const float4*)(&Bs[kk][tx * 4]);
            float a[8] = {a0.x, a0.y, a0.z, a0.w, a1.x, a1.y, a1.z, a1.w};
            float b[4] = {b4.x, b4.y, b4.z, b4.w};
#pragma unroll
            for (int i = 0; i < 8; i++)
#pragma unroll
                for (int j = 0; j < 4; j++) acc[i][j] = fmaf(a[i], b[j], acc[i][j]);
        }
        __syncthreads();
    }
#pragma unroll
    for (int i = 0; i < 8; i++) {
        int gm = m0 + ty * 8 + i;
        int gn = n0 + tx * 4;
        if (gm < INDIM) {
#pragma unroll
            for (int j = 0; j < 4; j++) g_W0[(size_t)(d * INDIM + gm) * HH + gn + j] = acc[i][j];
        } else if (gm == INDIM) {
#pragma unroll
            for (int j = 0; j < 4; j++) g_b0[d * HH + gn + j] = acc[i][j] + bx0[gn + j];
        }
    }
}

// ---------- X0 = x @ W0 + b0  (per direction) ----------
// grid (8, 256, 2), block 256.  M = 32768 rows (b*T+t), K = 300, N = 512
__global__ void x0_kernel(const float* __restrict__ x, const float* __restrict__ rx) {
    const int d = blockIdx.z;
    const float* A  = d ? rx : x;
    const float* Bw = g_W0 + (size_t)d * INDIM * HH;
    const int n0 = blockIdx.x * 64;
    const int m0 = blockIdx.y * 128;
    __shared__ float As[16][136];
    __shared__ float Bs[16][64];
    const int tid = threadIdx.x;
    const int ty = tid >> 4, tx = tid & 15;
    float acc[8][4];
#pragma unroll
    for (int i = 0; i < 8; i++)
#pragma unroll
        for (int j = 0; j < 4; j++) acc[i][j] = 0.f;

    for (int k0 = 0; k0 < INDIM; k0 += 16) {
        const bool full = (k0 + 16) <= INDIM;
        {
            const int row = tid >> 2, c4 = (tid & 3) * 4;
#pragma unroll
            for (int rr = 0; rr < 2; rr++) {
                int r = row + rr * 64;
                size_t gm = (size_t)(m0 + r);
                float4 av;
                if (full) {
                    av = *(const float4*)(A + gm * INDIM + k0 + c4);
                } else {
                    av.x = (k0 + c4 + 0 < INDIM) ? A[gm * INDIM + k0 + c4 + 0] : 0.f;
                    av.y = (k0 + c4 + 1 < INDIM) ? A[gm * INDIM + k0 + c4 + 1] : 0.f;
                    av.z = (k0 + c4 + 2 < INDIM) ? A[gm * INDIM + k0 + c4 + 2] : 0.f;
                    av.w = (k0 + c4 + 3 < INDIM) ? A[gm * INDIM + k0 + c4 + 3] : 0.f;
                }
                As[c4 + 0][r] = av.x; As[c4 + 1][r] = av.y;
                As[c4 + 2][r] = av.z; As[c4 + 3][r] = av.w;
            }
        }
        {
            const int row = tid >> 4, c4 = (tid & 15) * 4;
            float4 bv = make_float4(0.f, 0.f, 0.f, 0.f);
            if (k0 + row < INDIM) bv = *(const float4*)(Bw + (size_t)(k0 + row) * HH + n0 + c4);
            *(float4*)(&Bs[row][c4]) = bv;
        }
        __syncthreads();
#pragma unroll
        for (int kk = 0; kk < 16; kk++) {
            float4 a0 = *(const float4*)(&As[kk][ty * 8]);
            float4 a1 = *(const float4*)(&As[kk][ty * 8 + 4]);
            float4 b4 = *(const float4*)(&Bs[kk][tx * 4]);
            float a[8] = {a0.x, a0.y, a0.z, a0.w, a1.x, a1.y, a1.z, a1.w};
            float b[4] = {b4.x, b4.y, b4.z, b4.w};
#pragma unroll
            for (int i = 0; i < 8; i++)
#pragma unroll
                for (int j = 0; j < 4; j++) acc[i][j] = fmaf(a[i], b[j], acc[i][j]);
        }
        __syncthreads();
    }
#pragma unroll
    for (int i = 0; i < 8; i++) {
        int gm = m0 + ty * 8 + i;
        int bidx = gm >> 8;            // T = 256
        int t    = gm & 255;
        int gn = n0 + tx * 4;
        size_t base = ((size_t)(d * TT + t) * BB + bidx) * HH + gn;
#pragma unroll
        for (int j = 0; j < 4; j++) g_X0[base + j] = acc[i][j] + g_b0[d * HH + gn + j];
    }
}

// ---------- per-wavefront-step GEMM: partial pre-activations ----------
// grid (16, 8, 6), block 128.  Each CTA: 128x32 tile over a 128-wide K chunk.
__global__ void step_kernel(int s,
                            const float* __restrict__ Wx_l2r, const float* __restrict__ Wh_l2r,
                            const float* __restrict__ Wx_r2l, const float* __restrict__ Wh_r2l) {
    const int task = blockIdx.z;
    const int d = task / 3;
    const int l = task - d * 3;
    const int t = s - l;
    if (t < 0 || t >= TT) return;
    const int chunk = blockIdx.y;
    const float* Wxd = d ? Wx_r2l : Wx_l2r;
    const float* Whd = d ? Wh_r2l : Wh_l2r;
    const float* Ablk;
    const float* W;
    int koff;
    if (l == 0) {
        if (chunk >= 4) return;
        Ablk = g_h + (size_t)(d * 3 + 0) * BB * HH;
        W = Whd;                       // layer 0 slice at offset 0
        koff = chunk * 128;
    } else if (chunk < 4) {
        Ablk = g_h + (size_t)(d * 3 + l - 1) * BB * HH;
        W = Wxd + (size_t)l * HH * HH;
        koff = chunk * 128;
    } else {
        Ablk = g_h + (size_t)(d * 3 + l) * BB * HH;
        W = Whd + (size_t)l * HH * HH;
        koff = (chunk - 4) * 128;
    }
    const int n0 = blockIdx.x * 32;
    __shared__ float As[16][136];
    __shared__ float Bs[16][32];
    const int tid = threadIdx.x;
    const int ty = tid >> 3, tx = tid & 7;
    float acc[8][4];
#pragma unroll
    for (int i = 0; i < 8; i++)
#pragma unroll
        for (int j = 0; j < 4; j++) acc[i][j] = 0.f;

    for (int k0 = 0; k0 < 128; k0 += 16) {
        {
            const int row = tid >> 2, c4 = (tid & 3) * 4;
#pragma unroll
            for (int rr = 0; rr < 4; rr++) {
                int r = row + rr * 32;
                float4 av = *(const float4*)(Ablk + (size_t)r * HH + koff + k0 + c4);
                As[c4 + 0][r] = av.x; As[c4 + 1][r] = av.y;
                As[c4 + 2][r] = av.z; As[c4 + 3][r] = av.w;
            }
        }
        {
            const int row = tid >> 3, c4 = (tid & 7) * 4;
            float4 bv = *(const float4*)(W + (size_t)(koff + k0 + row) * HH + n0 + c4);
            *(float4*)(&Bs[row][c4]) = bv;
        }
        __syncthreads();
#pragma unroll
        for (int kk = 0; kk < 16; kk++) {
            float4 a0 = *(const float4*)(&As[kk][ty * 8]);
            float4 a1 = *(const float4*)(&As[kk][ty * 8 + 4]);
            float4 b4 = *(const float4*)(&Bs[kk][tx * 4]);
            float a[8] = {a0.x, a0.y, a0.z, a0.w, a1.x, a1.y, a1.z, a1.w};
            float b[4] = {b4.x, b4.y, b4.z, b4.w};
#pragma unroll
            for (int i = 0; i < 8; i++)
#pragma unroll
                for (int j = 0; j < 4; j++) acc[i][j] = fmaf(a[i], b[j], acc[i][j]);
        }
        __syncthreads();
    }
    float* out = g_pp + (size_t)((chunk * 2 + d) * 3 + l) * BB * HH;
#pragma unroll
    for (int i = 0; i < 8; i++) {
        *(float4*)(out + (size_t)(ty * 8 + i) * HH + n0 + tx * 4) =
            make_float4(acc[i][0], acc[i][1], acc[i][2], acc[i][3]);
    }
}

// ---------- per-step LayerNorm + tanh ----------
// grid (128, 6), block 256. One block per (batch row, task).
__global__ void ln_kernel(int s,
                          const float* __restrict__ bx_l2r, const float* __restrict__ bh_l2r,
                          const float* __restrict__ bx_r2l, const float* __restrict__ bh_r2l,
                          const float* __restrict__ ln_g,  const float* __restrict__ ln_b) {
    const int task = blockIdx.y;
    const int d = task / 3;
    const int l = task - d * 3;
    const int t = s - l;
    if (t < 0 || t >= TT) return;
    const int b = blockIdx.x;
    const float* bx = (d ? bx_r2l : bx_l2r) + l * HH;
    const float* bh = (d ? bh_r2l : bh_l2r) + l * HH;
    const int nch = (l == 0) ? 4 : 8;
    const int tid = threadIdx.x;

    float v[2];
    float s1 = 0.f, s2 = 0.f;
#pragma unroll
    for (int e = 0; e < 2; e++) {
        int j = tid + e * 256;
        float val = bh[j];
        if (l == 0) val += g_X0[((size_t)(d * TT + t) * BB + b) * HH + j];
        else        val += bx[j];
        for (int c = 0; c < nch; c++)
            val += g_pp[(size_t)((c * 2 + d) * 3 + l) * BB * HH + (size_t)b * HH + j];
        v[e] = val;
        s1 += val;
        s2 += val * val;
    }
    __shared__ float r1[256], r2[256];
    r1[tid] = s1; r2[tid] = s2;
    __syncthreads();
    for (int off = 128; off > 0; off >>= 1) {
        if (tid < off) { r1[tid] += r1[tid + off]; r2[tid] += r2[tid + off]; }
        __syncthreads();
    }
    const float mean = r1[0] * (1.f / HH);
    const float var  = r2[0] * (1.f / HH) - mean * mean;
    const float inv  = rsqrtf(var + LNEPS);
#pragma unroll
    for (int e = 0; e < 2; e++) {
        int j = tid + e * 256;
        float hn = tanhf((v[e] - mean) * inv * ln_g[l * HH + j] + ln_b[l * HH + j]);
        g_h[(size_t)(d * 3 + l) * BB * HH + (size_t)b * HH + j] = hn;
        if (l == 2) g_o2[((size_t)(d * TT + t) * BB + b) * HH + j] = hn;
    }
}

// ---------- gather + concat + FC ----------
// grid (8192), block 256: 4 output rows per block, 64 threads per row.
__global__ void final_kernel(const int* __restrict__ pad,
                             const float* __restrict__ W_fc, const float* __restrict__ b_fc,
                             float* __restrict__ out) {
    __shared__ float cs[4][1024];
    const int sub  = threadIdx.x >> 6;
    const int lane = threadIdx.x & 63;
    const int r = blockIdx.x * 4 + sub;
    const int b = r >> 8;        // T = 256
    const int t = r & 255;
    const int p = pad[b];
    const int tt = (t < p) ? (p - t - 1) : t;
    const float* a0 = g_o2 + ((size_t)(0 * TT + t)  * BB + b) * HH;
    const float* a1 = g_o2 + ((size_t)(1 * TT + tt) * BB + b) * HH;
#pragma unroll
    for (int i = 0; i < 4; i++) {
        int j = lane * 4 + i * 256;
        float4 vv = (j < 512) ? *(const float4*)(a0 + j) : *(const float4*)(a1 + j - 512);
        *(float4*)(&cs[sub][j]) = vv;
    }
    __syncthreads();
    if (lane < NCLS) {
        float acc = b_fc[lane];
#pragma unroll 8
        for (int k = 0; k < 1024; k++) acc = fmaf(cs[sub][k], W_fc[k * NCLS + lane], acc);
        out[(size_t)r * NCLS + lane] = acc;
    }
}

// ---------- host launcher ----------
extern "C" void kernel_launch(void* const* d_in, const int* in_sizes, int n_in,
                              void* d_out, int out_size) {
    (void)in_sizes; (void)n_in; (void)out_size;
    const float* x      = (const float*)d_in[0];
    const float* rx     = (const float*)d_in[1];
    const int*   pad    = (const int*)  d_in[2];
    // d_in[3] = max_length (always 256 for this shape)
    const float* W_emb  = (const float*)d_in[4];
    const float* b_emb  = (const float*)d_in[5];
    const float* Wx_l2r = (const float*)d_in[6];
    const float* bx_l2r = (const float*)d_in[7];
    const float* Wh_l2r = (const float*)d_in[8];
    const float* bh_l2r = (const float*)d_in[9];
    const float* Wx_r2l = (const float*)d_in[10];
    const float* bx_r2l = (const float*)d_in[11];
    const float* Wh_r2l = (const float*)d_in[12];
    const float* bh_r2l = (const float*)d_in[13];
    const float* ln_g   = (const float*)d_in[14];
    const float* ln_b   = (const float*)d_in[15];
    const float* W_fc   = (const float*)d_in[16];
    const float* b_fc   = (const float*)d_in[17];
    float* out = (float*)d_out;

    zero_h_kernel<<<(2 * 3 * BB * HH + 255) / 256, 256>>>();
    w0_kernel<<<dim3(8, 3, 2), 256>>>(W_emb, b_emb, Wx_l2r, bx_l2r, Wx_r2l, bx_r2l);
    x0_kernel<<<dim3(8, 256, 2), 256>>>(x, rx);

    for (int s = 0; s < TT + 2; s++) {
        step_kernel<<<dim3(16, 8, 6), 128>>>(s, Wx_l2r, Wh_l2r, Wx_r2l, Wh_r2l);
        ln_kernel<<<dim3(128, 6), 256>>>(s, bx_l2r, bh_l2r, bx_r2l, bh_r2l, ln_g, ln_b);
    }

    final_kernel<<<8192, 256>>>(pad, W_fc, b_fc, out);
}

// round 5
// speedup vs baseline: 1.4356x; 1.4297x over previous
#include <cuda_runtime.h>
#include <cuda_bf16.h>
#include <math.h>
#include <stdint.h>

#define BB    128
#define TT    256
#define INDIM 300
#define HH    512
#define NCLS  45
#define LNEPS 1e-5f

#define GRID_P  148
#define NTILES  80
#define NSTEPS  258

// dynamic smem layout (byte offsets)
#define SM_A   0
#define SM_B0  65536
#define SM_B1  131072
#define DSMEM  196608

// ---------- device scratch ----------
__device__ float g_W0[2 * INDIM * HH];
__device__ float g_b0[2 * HH];
__device__ float g_X0[2 * TT * BB * HH];
__device__ __align__(16) __nv_bfloat16 g_Bh[10 * HH * HH];   // weights transposed [mat][n][k], hi
__device__ __align__(16) __nv_bfloat16 g_Bl[10 * HH * HH];   // lo
__device__ __align__(16) __nv_bfloat16 g_hh[2 * 3 * BB * HH];
__device__ __align__(16) __nv_bfloat16 g_hl[2 * 3 * BB * HH];
__device__ float g_pp[2 * 3 * 4 * 2 * BB * HH];              // partials [(d*3+l)*8 + kc*2 + prod][b][n]
__device__ float g_o2[2 * TT * BB * HH];
__device__ unsigned g_barc;
__device__ unsigned g_sense;

// ---------- helpers ----------
__device__ __forceinline__ uint32_t smem_u32(const void* p) {
    uint32_t a;
    asm("{ .reg .u64 t; cvta.to.shared.u64 t, %1; cvt.u32.u64 %0, t; }" : "=r"(a) : "l"(p));
    return a;
}

// grid barrier: release-arrive, acquire-poll, reader-side L1 invalidate
__device__ __forceinline__ void gsync(unsigned target) {
    __syncthreads();
    if (threadIdx.x == 0) {
        unsigned old;
        asm volatile("atom.add.acq_rel.gpu.u32 %0, [%1], 1;" : "=r"(old) : "l"(&g_barc) : "memory");
        if (old == (unsigned)(GRID_P - 1)) {
            asm volatile("st.relaxed.gpu.u32 [%0], 0;" :: "l"(&g_barc) : "memory");
            asm volatile("st.release.gpu.u32 [%0], %1;" :: "l"(&g_sense), "r"(target) : "memory");
        } else {
            unsigned sv;
            do {
                asm volatile("ld.acquire.gpu.u32 %0, [%1];" : "=r"(sv) : "l"(&g_sense) : "memory");
            } while (sv != target);
        }
        __threadfence();   // CCTL.IVALL: invalidate this SM's L1 so h/pp reads are fresh
    }
    __syncthreads();
}

// ---------- init ----------
__global__ void init_kernel() {
    int i = blockIdx.x * blockDim.x + threadIdx.x;
    if (i == 0) { g_barc = 0; g_sense = 0; }
    if (i < 2 * 3 * BB * HH) {
        g_hh[i] = __float2bfloat16(0.f);
        g_hl[i] = __float2bfloat16(0.f);
    }
}

// ---------- W0 = [W_emb; b_emb] @ Wx0 (+bx0) ----------
__global__ void w0_kernel(const float* __restrict__ W_emb, const float* __restrict__ b_emb,
                          const float* __restrict__ Wx_l2r, const float* __restrict__ bx_l2r,
                          const float* __restrict__ Wx_r2l, const float* __restrict__ bx_r2l) {
    const int d = blockIdx.z;
    const float* Wx0 = d ? Wx_r2l : Wx_l2r;
    const float* bx0 = d ? bx_r2l : bx_l2r;
    const int n0 = blockIdx.x * 64;
    const int m0 = blockIdx.y * 128;
    __shared__ float As[16][136];
    __shared__ float Bs[16][64];
    const int tid = threadIdx.x;
    const int ty = tid >> 4, tx = tid & 15;
    float acc[8][4];
#pragma unroll
    for (int i = 0; i < 8; i++)
#pragma unroll
        for (int j = 0; j < 4; j++) acc[i][j] = 0.f;

    for (int k0 = 0; k0 < HH; k0 += 16) {
        {
            const int row = tid >> 2, c4 = (tid & 3) * 4;
#pragma unroll
            for (int rr = 0; rr < 2; rr++) {
                int r = row + rr * 64;
                int gm = m0 + r;
                float4 av = make_float4(0.f, 0.f, 0.f, 0.f);
                if (gm < INDIM)       av = *(const float4*)(W_emb + (size_t)gm * HH + k0 + c4);
                else if (gm == INDIM) av = *(const float4*)(b_emb + k0 + c4);
                As[c4 + 0][r] = av.x; As[c4 + 1][r] = av.y;
                As[c4 + 2][r] = av.z; As[c4 + 3][r] = av.w;
            }
        }
        {
            const int row = tid >> 4, c4 = (tid & 15) * 4;
            float4 bv = *(const float4*)(Wx0 + (size_t)(k0 + row) * HH + n0 + c4);
            *(float4*)(&Bs[row][c4]) = bv;
        }
        __syncthreads();
#pragma unroll
        for (int kk = 0; kk < 16; kk++) {
            float4 a0 = *(const float4*)(&As[kk][ty * 8]);
            float4 a1 = *(const float4*)(&As[kk][ty * 8 + 4]);
            float4 b4 = *(const float4*)(&Bs[kk][tx * 4]);
            float a[8] = {a0.x, a0.y, a0.z, a0.w, a1.x, a1.y, a1.z, a1.w};
            float b[4] = {b4.x, b4.y, b4.z, b4.w};
#pragma unroll
            for (int i = 0; i < 8; i++)
#pragma unroll
                for (int j = 0; j < 4; j++) acc[i][j] = fmaf(a[i], b[j], acc[i][j]);
        }
        __syncthreads();
    }
#pragma unroll
    for (int i = 0; i < 8; i++) {
        int gm = m0 + ty * 8 + i;
        int gn = n0 + tx * 4;
        if (gm < INDIM) {
#pragma unroll
            for (int j = 0; j < 4; j++) g_W0[(size_t)(d * INDIM + gm) * HH + gn + j] = acc[i][j];
        } else if (gm == INDIM) {
#pragma unroll
            for (int j = 0; j < 4; j++) g_b0[d * HH + gn + j] = acc[i][j] + bx0[gn + j];
        }
    }
}

// ---------- X0 = x @ W0 + b0 ----------
__global__ void x0_kernel(const float* __restrict__ x, const float* __restrict__ rx) {
    const int d = blockIdx.z;
    const float* A  = d ? rx : x;
    const float* Bw = g_W0 + (size_t)d * INDIM * HH;
    const int n0 = blockIdx.x * 64;
    const int m0 = blockIdx.y * 128;
    __shared__ float As[16][136];
    __shared__ float Bs[16][64];
    const int tid = threadIdx.x;
    const int ty = tid >> 4, tx = tid & 15;
    float acc[8][4];
#pragma unroll
    for (int i = 0; i < 8; i++)
#pragma unroll
        for (int j = 0; j < 4; j++) acc[i][j] = 0.f;

    for (int k0 = 0; k0 < INDIM; k0 += 16) {
        const bool full = (k0 + 16) <= INDIM;
        {
            const int row = tid >> 2, c4 = (tid & 3) * 4;
#pragma unroll
            for (int rr = 0; rr < 2; rr++) {
                int r = row + rr * 64;
                size_t gm = (size_t)(m0 + r);
                float4 av;
                if (full) {
                    av = *(const float4*)(A + gm * INDIM + k0 + c4);
                } else {
                    av.x = (k0 + c4 + 0 < INDIM) ? A[gm * INDIM + k0 + c4 + 0] : 0.f;
                    av.y = (k0 + c4 + 1 < INDIM) ? A[gm * INDIM + k0 + c4 + 1] : 0.f;
                    av.z = (k0 + c4 + 2 < INDIM) ? A[gm * INDIM + k0 + c4 + 2] : 0.f;
                    av.w = (k0 + c4 + 3 < INDIM) ? A[gm * INDIM + k0 + c4 + 3] : 0.f;
                }
                As[c4 + 0][r] = av.x; As[c4 + 1][r] = av.y;
                As[c4 + 2][r] = av.z; As[c4 + 3][r] = av.w;
            }
        }
        {
            const int row = tid >> 4, c4 = (tid & 15) * 4;
            float4 bv = make_float4(0.f, 0.f, 0.f, 0.f);
            if (k0 + row < INDIM) bv = *(const float4*)(Bw + (size_t)(k0 + row) * HH + n0 + c4);
            *(float4*)(&Bs[row][c4]) = bv;
        }
        __syncthreads();
#pragma unroll
        for (int kk = 0; kk < 16; kk++) {
            float4 a0 = *(const float4*)(&As[kk][ty * 8]);
            float4 a1 = *(const float4*)(&As[kk][ty * 8 + 4]);
            float4 b4 = *(const float4*)(&Bs[kk][tx * 4]);
            float a[8] = {a0.x, a0.y, a0.z, a0.w, a1.x, a1.y, a1.z, a1.w};
            float b[4] = {b4.x, b4.y, b4.z, b4.w};
#pragma unroll
            for (int i = 0; i < 8; i++)
#pragma unroll
                for (int j = 0; j < 4; j++) acc[i][j] = fmaf(a[i], b[j], acc[i][j]);
        }
        __syncthreads();
    }
#pragma unroll
    for (int i = 0; i < 8; i++) {
        int gm = m0 + ty * 8 + i;
        int bidx = gm >> 8;
        int t    = gm & 255;
        int gn = n0 + tx * 4;
        size_t base = ((size_t)(d * TT + t) * BB + bidx) * HH + gn;
#pragma unroll
        for (int j = 0; j < 4; j++) g_X0[base + j] = acc[i][j] + g_b0[d * HH + gn + j];
    }
}

// ---------- weights -> transposed bf16 hi/lo. mats/dir: 0=Wh0,1=Wx1,2=Wh1,3=Wx2,4=Wh2 ----------
__global__ void convw_kernel(const float* __restrict__ Wx_l2r, const float* __restrict__ Wh_l2r,
                             const float* __restrict__ Wx_r2l, const float* __restrict__ Wh_r2l) {
    const int mat = blockIdx.z;
    const int d = mat / 5, mm = mat % 5;
    const float* Wx = d ? Wx_r2l : Wx_l2r;
    const float* Wh = d ? Wh_r2l : Wh_l2r;
    const float* W;
    if      (mm == 0) W = Wh;
    else if (mm == 1) W = Wx + (size_t)1 * HH * HH;
    else if (mm == 2) W = Wh + (size_t)1 * HH * HH;
    else if (mm == 3) W = Wx + (size_t)2 * HH * HH;
    else              W = Wh + (size_t)2 * HH * HH;

    __shared__ float tile[32][33];
    const int k0 = blockIdx.y * 32, n0 = blockIdx.x * 32;
    for (int r = threadIdx.y; r < 32; r += 8)
        tile[r][threadIdx.x] = W[(size_t)(k0 + r) * HH + n0 + threadIdx.x];
    __syncthreads();
    for (int r = threadIdx.y; r < 32; r += 8) {
        float v = tile[threadIdx.x][r];     // W[k0+tx][n0+r]
        __nv_bfloat16 hi = __float2bfloat16(v);
        __nv_bfloat16 lo = __float2bfloat16(v - __bfloat162float(hi));
        size_t dst = ((size_t)mat * HH + n0 + r) * HH + k0 + threadIdx.x;
        g_Bh[dst] = hi;
        g_Bl[dst] = lo;
    }
}

// ---------- stage a 128-row x 256-col bf16 tile (row stride HH) into XOR-swizzled smem ----------
// layout: byte(r, kchunk16B c) = r*512 + ((c ^ (r&7))*16)
__device__ __forceinline__ void load_tile(uint32_t sm_dst, const __nv_bfloat16* __restrict__ src) {
    const int tid = threadIdx.x;
#pragma unroll
    for (int it = 0; it < 16; it++) {
        int idx = it * 256 + tid;
        int r = idx >> 5;
        int c = idx & 31;
        uint4 v = *(const uint4*)(src + (size_t)r * HH + c * 8);
        uint32_t dst = sm_dst + r * 512 + (((uint32_t)(c ^ (r & 7))) << 4);
        asm volatile("st.shared.v4.b32 [%0], {%1,%2,%3,%4};"
                     :: "r"(dst), "r"(v.x), "r"(v.y), "r"(v.z), "r"(v.w) : "memory");
    }
}

// ---------- warp GEMM pass: acc[2][8][4] += smA(128x256) @ smB(128n x 256k)^T ----------
__device__ __forceinline__ void gemm_pass(uint32_t smA, uint32_t smB,
                                          const int aoff[2], const int aswz[2], int ahi,
                                          const int boff[4], const int bswz[4], int bhi,
                                          float acc[2][8][4], bool fresh) {
    if (fresh) {
#pragma unroll
        for (int mt = 0; mt < 2; mt++)
#pragma unroll
            for (int nt = 0; nt < 8; nt++)
#pragma unroll
                for (int i = 0; i < 4; i++) acc[mt][nt][i] = 0.f;
    }
#pragma unroll 4
    for (int ks = 0; ks < 16; ks++) {
        uint32_t a[2][4];
#pragma unroll
        for (int mt = 0; mt < 2; mt++) {
            uint32_t addr = smA + aoff[mt] + ((uint32_t)((ks * 2 + ahi) ^ aswz[mt]) << 4);
            asm volatile("ldmatrix.sync.aligned.m8n8.x4.shared.b16 {%0,%1,%2,%3}, [%4];"
                         : "=r"(a[mt][0]), "=r"(a[mt][1]), "=r"(a[mt][2]), "=r"(a[mt][3])
                         : "r"(addr));
        }
        uint32_t bq[4][4];
#pragma unroll
        for (int np = 0; np < 4; np++) {
            uint32_t addr = smB + boff[np] + ((uint32_t)((ks * 2 + bhi) ^ bswz[np]) << 4);
            asm volatile("ldmatrix.sync.aligned.m8n8.x4.shared.b16 {%0,%1,%2,%3}, [%4];"
                         : "=r"(bq[np][0]), "=r"(bq[np][1]), "=r"(bq[np][2]), "=r"(bq[np][3])
                         : "r"(addr));
        }
#pragma unroll
        for (int mt = 0; mt < 2; mt++)
#pragma unroll
            for (int nt = 0; nt < 8; nt++) {
                uint32_t b0 = bq[nt >> 1][(nt & 1) ? 2 : 0];
                uint32_t b1 = bq[nt >> 1][(nt & 1) ? 3 : 1];
                asm volatile(
                    "mma.sync.aligned.m16n8k16.row.col.f32.bf16.bf16.f32 "
                    "{%0,%1,%2,%3}, {%4,%5,%6,%7}, {%8,%9}, {%0,%1,%2,%3};"
                    : "+f"(acc[mt][nt][0]), "+f"(acc[mt][nt][1]),
                      "+f"(acc[mt][nt][2]), "+f"(acc[mt][nt][3])
                    : "r"(a[mt][0]), "r"(a[mt][1]), "r"(a[mt][2]), "r"(a[mt][3]),
                      "r"(b0), "r"(b1));
            }
    }
}

// ---------- persistent wavefront kernel ----------
__global__ void __launch_bounds__(256, 1)
persist_kernel(const float* __restrict__ bx_l2r, const float* __restrict__ bh_l2r,
               const float* __restrict__ bx_r2l, const float* __restrict__ bh_r2l,
               const float* __restrict__ ln_g,  const float* __restrict__ ln_b) {
    extern __shared__ char smem_raw[];
    const uint32_t sbase = smem_u32(smem_raw);
    const int tid = threadIdx.x;
    const int wid = tid >> 5, lane = tid & 31;
    const int wm = wid & 3, wn = wid >> 2;
    __shared__ float red[2][8];

    // per-lane ldmatrix address components
    int aoff[2], aswz[2];
#pragma unroll
    for (int mt = 0; mt < 2; mt++) {
        int r = wm * 32 + mt * 16 + (lane & 15);
        aoff[mt] = r * 512;
        aswz[mt] = r & 7;
    }
    const int ahi = lane >> 4;
    int boff[4], bswz[4];
#pragma unroll
    for (int np = 0; np < 4; np++) {
        int nl = wn * 64 + np * 16 + (lane & 7) + ((lane >> 4) << 3);
        boff[np] = nl * 512;
        bswz[np] = nl & 7;
    }
    const int bhi = (lane >> 3) & 1;

    // ---- decode work items ----
    // tile idx 0..79 -> (d,l,ntile,kc,mat,asrc,koff,n0)
    auto decode = [](int tile, int& d, int& l, int& ntile, int& kc,
                     int& mat, int& asrc, int& koff) {
        d = tile / 40;
        int r = tile % 40;
        if (r < 8)       { l = 0; ntile = r >> 1;        kc = r & 1; }
        else if (r < 24) { l = 1; ntile = (r - 8) >> 2;  kc = (r - 8) & 3; }
        else             { l = 2; ntile = (r - 24) >> 2; kc = (r - 24) & 3; }
        if (l == 0)      { mat = d * 5 + 0;         asrc = 0;     koff = kc * 256; }
        else if (kc < 2) { mat = d * 5 + 2 * l - 1; asrc = l - 1; koff = kc * 256; }
        else             { mat = d * 5 + 2 * l;     asrc = l;     koff = (kc - 2) * 256; }
    };

    // up to 2 passes per CTA
    const __nv_bfloat16* pA[2] = {nullptr, nullptr};
    uint32_t pB[2];
    float* pDst[2] = {nullptr, nullptr};
    int pL[2] = {0, 0};
    bool pFresh[2], pStore[2], pLoadA[2];
    int npass = 0;

    const int cta = blockIdx.x;
    if (cta < NTILES) {
        // heavy: Ah x Bh + Ah x Bl, one tile, slot prod=0
        int d, l, ntile, kc, mat, asrc, koff;
        decode(cta, d, l, ntile, kc, mat, asrc, koff);
        int n0 = ntile * 128;
        load_tile(sbase + SM_B0, g_Bh + ((size_t)mat * HH + n0) * HH + koff);
        load_tile(sbase + SM_B1, g_Bl + ((size_t)mat * HH + n0) * HH + koff);
        const __nv_bfloat16* a = g_hh + (size_t)(d * 3 + asrc) * BB * HH + koff;
        float* dst = g_pp + (size_t)((d * 3 + l) * 8 + kc * 2 + 0) * (BB * HH) + n0;
        pA[0] = a;  pB[0] = sbase + SM_B0; pDst[0] = nullptr; pL[0] = l;
        pFresh[0] = true;  pStore[0] = false; pLoadA[0] = true;
        pA[1] = a;  pB[1] = sbase + SM_B1; pDst[1] = dst;     pL[1] = l;
        pFresh[1] = false; pStore[1] = true;  pLoadA[1] = false;
        npass = 2;
    } else {
        // light: Al x Bh, 1 or 2 tiles, slot prod=1
        int j = cta - NTILES;
        int units[2] = {j, (j < 12) ? (68 + j) : -1};
        for (int q = 0; q < 2; q++) {
            if (units[q] < 0) break;
            int d, l, ntile, kc, mat, asrc, koff;
            decode(units[q], d, l, ntile, kc, mat, asrc, koff);
            int n0 = ntile * 128;
            uint32_t sb = sbase + (q ? SM_B1 : SM_B0);
            load_tile(sb, g_Bh + ((size_t)mat * HH + n0) * HH + koff);
            pA[q] = g_hl + (size_t)(d * 3 + asrc) * BB * HH + koff;
            pB[q] = sb;
            pDst[q] = g_pp + (size_t)((d * 3 + l) * 8 + kc * 2 + 1) * (BB * HH) + n0;
            pL[q] = l;
            pFresh[q] = true; pStore[q] = true; pLoadA[q] = true;
            npass = q + 1;
        }
    }
    __syncthreads();

    // epilogue store lane mapping
    const int er = lane >> 2, ec = (lane & 3) * 2;

    float acc[2][8][4];
    unsigned bt = 0;

    for (int s = 0; s < NSTEPS; s++) {
        for (int p = 0; p < npass; p++) {
            const int t = s - pL[p];
            if (t < 0 || t >= TT) continue;
            if (pLoadA[p]) {
                __syncthreads();                 // protect SM_A from readers of prior pass
                load_tile(sbase + SM_A, pA[p]);
                __syncthreads();
            }
            gemm_pass(sbase + SM_A, pB[p], aoff, aswz, ahi, boff, bswz, bhi, acc, pFresh[p]);
            if (pStore[p]) {
                float* dst = pDst[p];
#pragma unroll
                for (int mt = 0; mt < 2; mt++) {
                    int row0 = wm * 32 + mt * 16 + er;
#pragma unroll
                    for (int nt = 0; nt < 8; nt++) {
                        int col = wn * 64 + nt * 8 + ec;
                        *(float2*)(dst + (size_t)row0 * HH + col) =
                            make_float2(acc[mt][nt][0], acc[mt][nt][1]);
                        *(float2*)(dst + (size_t)(row0 + 8) * HH + col) =
                            make_float2(acc[mt][nt][2], acc[mt][nt][3]);
                    }
                }
            }
        }

        gsync(++bt);

        // ---- LN + tanh: 768 rows strided over grid ----
        for (int row = blockIdx.x; row < 768; row += GRID_P) {
            const int task = row >> 7, b = row & 127;
            const int dd = task / 3, ll = task - dd * 3;
            const int tt2 = s - ll;
            if (tt2 < 0 || tt2 >= TT) continue;
            const float* bxp = (dd ? bx_r2l : bx_l2r) + ll * HH;
            const float* bhp = (dd ? bh_r2l : bh_l2r) + ll * HH;
            const int nch = (ll == 0) ? 4 : 8;
            const int slotbase = (dd * 3 + ll) * 8;
            float v[2], s1 = 0.f, s2 = 0.f;
#pragma unroll
            for (int e = 0; e < 2; e++) {
                int j = tid + e * 256;
                float val = bhp[j];
                if (ll == 0) val += g_X0[((size_t)(dd * TT + tt2) * BB + b) * HH + j];
                else         val += bxp[j];
                for (int c = 0; c < nch; c++)
                    val += g_pp[(size_t)(slotbase + c) * (BB * HH) + (size_t)b * HH + j];
                v[e] = val;
                s1 += val;
                s2 += val * val;
            }
#pragma unroll
            for (int o = 16; o > 0; o >>= 1) {
                s1 += __shfl_xor_sync(0xffffffffu, s1, o);
                s2 += __shfl_xor_sync(0xffffffffu, s2, o);
            }
            if (lane == 0) { red[0][wid] = s1; red[1][wid] = s2; }
            __syncthreads();
            float t1 = 0.f, t2 = 0.f;
#pragma unroll
            for (int w = 0; w < 8; w++) { t1 += red[0][w]; t2 += red[1][w]; }
            const float mean = t1 * (1.f / HH);
            const float var  = t2 * (1.f / HH) - mean * mean;
            const float inv  = rsqrtf(var + LNEPS);
#pragma unroll
            for (int e = 0; e < 2; e++) {
                int j = tid + e * 256;
                float hn = tanhf((v[e] - mean) * inv * ln_g[ll * HH + j] + ln_b[ll * HH + j]);
                __nv_bfloat16 hi = __float2bfloat16(hn);
                __nv_bfloat16 lo = __float2bfloat16(hn - __bfloat162float(hi));
                size_t hidx = (size_t)(dd * 3 + ll) * BB * HH + (size_t)b * HH + j;
                g_hh[hidx] = hi;
                g_hl[hidx] = lo;
                if (ll == 2) g_o2[((size_t)(dd * TT + tt2) * BB + b) * HH + j] = hn;
            }
            __syncthreads();
        }

        gsync(++bt);
    }
}

// ---------- gather + concat + FC ----------
__global__ void final_kernel(const int* __restrict__ pad,
                             const float* __restrict__ W_fc, const float* __restrict__ b_fc,
                             float* __restrict__ out) {
    __shared__ float cs[4][1024];
    const int sub  = threadIdx.x >> 6;
    const int lane = threadIdx.x & 63;
    const int r = blockIdx.x * 4 + sub;
    const int b = r >> 8;
    const int t = r & 255;
    const int p = pad[b];
    const int tt = (t < p) ? (p - t - 1) : t;
    const float* a0 = g_o2 + ((size_t)(0 * TT + t)  * BB + b) * HH;
    const float* a1 = g_o2 + ((size_t)(1 * TT + tt) * BB + b) * HH;
#pragma unroll
    for (int i = 0; i < 4; i++) {
        int j = lane * 4 + i * 256;
        float4 vv = (j < 512) ? *(const float4*)(a0 + j) : *(const float4*)(a1 + j - 512);
        *(float4*)(&cs[sub][j]) = vv;
    }
    __syncthreads();
    if (lane < NCLS) {
        float acc = b_fc[lane];
#pragma unroll 8
        for (int k = 0; k < 1024; k++) acc = fmaf(cs[sub][k], W_fc[k * NCLS + lane], acc);
        out[(size_t)r * NCLS + lane] = acc;
    }
}

// ---------- host launcher ----------
extern "C" void kernel_launch(void* const* d_in, const int* in_sizes, int n_in,
                              void* d_out, int out_size) {
    (void)in_sizes; (void)n_in; (void)out_size;
    const float* x      = (const float*)d_in[0];
    const float* rx     = (const float*)d_in[1];
    const int*   pad    = (const int*)  d_in[2];
    const float* W_emb  = (const float*)d_in[4];
    const float* b_emb  = (const float*)d_in[5];
    const float* Wx_l2r = (const float*)d_in[6];
    const float* bx_l2r = (const float*)d_in[7];
    const float* Wh_l2r = (const float*)d_in[8];
    const float* bh_l2r = (const float*)d_in[9];
    const float* Wx_r2l = (const float*)d_in[10];
    const float* bx_r2l = (const float*)d_in[11];
    const float* Wh_r2l = (const float*)d_in[12];
    const float* bh_r2l = (const float*)d_in[13];
    const float* ln_g   = (const float*)d_in[14];
    const float* ln_b   = (const float*)d_in[15];
    const float* W_fc   = (const float*)d_in[16];
    const float* b_fc   = (const float*)d_in[17];
    float* out = (float*)d_out;

    static int attr_done = 0;
    if (!attr_done) {
        cudaFuncSetAttribute(persist_kernel, cudaFuncAttributeMaxDynamicSharedMemorySize, DSMEM);
        attr_done = 1;
    }

    init_kernel<<<(2 * 3 * BB * HH + 255) / 256, 256>>>();
    w0_kernel<<<dim3(8, 3, 2), 256>>>(W_emb, b_emb, Wx_l2r, bx_l2r, Wx_r2l, bx_r2l);
    x0_kernel<<<dim3(8, 256, 2), 256>>>(x, rx);
    convw_kernel<<<dim3(16, 16, 10), dim3(32, 8)>>>(Wx_l2r, Wh_l2r, Wx_r2l, Wh_r2l);

    persist_kernel<<<GRID_P, 256, DSMEM>>>(bx_l2r, bh_l2r, bx_r2l, bh_r2l, ln_g, ln_b);

    final_kernel<<<8192, 256>>>(pad, W_fc, b_fc, out);
}

// round 6
// speedup vs baseline: 1.5953x; 1.1112x over previous
#include <cuda_runtime.h>
#include <cuda_bf16.h>
#include <math.h>
#include <stdint.h>

#define BB    128
#define TT    256
#define INDIM 300
#define HH    512
#define NCLS  45
#define LNEPS 1e-5f

#define GRID_P  148
#define NTILES  80
#define NSTEPS  258

// dynamic smem layout (byte offsets)
#define SM_A   0
#define SM_B0  65536
#define SM_B1  131072
#define DSMEM  196608

// ---------- device scratch ----------
__device__ float g_W0[2 * INDIM * HH];
__device__ float g_b0[2 * HH];
__device__ float g_X0[2 * TT * BB * HH];
__device__ __align__(16) __nv_bfloat16 g_Bh[10 * HH * HH];   // weights transposed [mat][n][k], hi
__device__ __align__(16) __nv_bfloat16 g_Bl[10 * HH * HH];   // lo
__device__ __align__(16) __nv_bfloat16 g_hh[2 * 3 * BB * HH];
__device__ __align__(16) __nv_bfloat16 g_hl[2 * 3 * BB * HH];
__device__ float g_pp[2 * 3 * 4 * 2 * BB * HH];              // partials [(d*3+l)*8 + kc*2 + prod][b][n]
__device__ float g_o2[2 * TT * BB * HH];
__device__ float g_cb[6 * HH];                               // combined LN input bias per task
__device__ unsigned g_barc;
__device__ unsigned g_sense;

// ---------- helpers ----------
__device__ __forceinline__ uint32_t smem_u32(const void* p) {
    uint32_t a;
    asm("{ .reg .u64 t; cvta.to.shared.u64 t, %1; cvt.u32.u64 %0, t; }" : "=r"(a) : "l"(p));
    return a;
}

// grid barrier: release-arrive, acquire-poll, reader-side L1 invalidate
__device__ __forceinline__ void gsync(unsigned target) {
    __syncthreads();
    if (threadIdx.x == 0) {
        unsigned old;
        asm volatile("atom.add.acq_rel.gpu.u32 %0, [%1], 1;" : "=r"(old) : "l"(&g_barc) : "memory");
        if (old == (unsigned)(GRID_P - 1)) {
            asm volatile("st.relaxed.gpu.u32 [%0], 0;" :: "l"(&g_barc) : "memory");
            asm volatile("st.release.gpu.u32 [%0], %1;" :: "l"(&g_sense), "r"(target) : "memory");
        } else {
            unsigned sv;
            do {
                asm volatile("ld.acquire.gpu.u32 %0, [%1];" : "=r"(sv) : "l"(&g_sense) : "memory");
            } while (sv != target);
        }
        __threadfence();   // CCTL.IVALL: invalidate this SM's L1 so h/pp reads are fresh
    }
    __syncthreads();
}

// ---------- init: zero h, zero barrier, build combined bias ----------
__global__ void init_kernel(const float* __restrict__ bx_l2r, const float* __restrict__ bh_l2r,
                            const float* __restrict__ bx_r2l, const float* __restrict__ bh_r2l) {
    int i = blockIdx.x * blockDim.x + threadIdx.x;
    if (i == 0) { g_barc = 0; g_sense = 0; }
    if (i < 2 * 3 * BB * HH) {
        g_hh[i] = __float2bfloat16(0.f);
        g_hl[i] = __float2bfloat16(0.f);
    }
    if (i < 6 * HH) {
        int task = i / HH, j = i % HH;
        int dd = task / 3, ll = task - dd * 3;
        const float* bx = dd ? bx_r2l : bx_l2r;
        const float* bh = dd ? bh_r2l : bh_l2r;
        float cb = bh[ll * HH + j];
        if (ll != 0) cb += bx[ll * HH + j];   // l0's bx is folded into X0
        g_cb[i] = cb;
    }
}

// ---------- W0 = [W_emb; b_emb] @ Wx0 (+bx0) ----------
__global__ void w0_kernel(const float* __restrict__ W_emb, const float* __restrict__ b_emb,
                          const float* __restrict__ Wx_l2r, const float* __restrict__ bx_l2r,
                          const float* __restrict__ Wx_r2l, const float* __restrict__ bx_r2l) {
    const int d = blockIdx.z;
    const float* Wx0 = d ? Wx_r2l : Wx_l2r;
    const float* bx0 = d ? bx_r2l : bx_l2r;
    const int n0 = blockIdx.x * 64;
    const int m0 = blockIdx.y * 128;
    __shared__ float As[16][136];
    __shared__ float Bs[16][64];
    const int tid = threadIdx.x;
    const int ty = tid >> 4, tx = tid & 15;
    float acc[8][4];
#pragma unroll
    for (int i = 0; i < 8; i++)
#pragma unroll
        for (int j = 0; j < 4; j++) acc[i][j] = 0.f;

    for (int k0 = 0; k0 < HH; k0 += 16) {
        {
            const int row = tid >> 2, c4 = (tid & 3) * 4;
#pragma unroll
            for (int rr = 0; rr < 2; rr++) {
                int r = row + rr * 64;
                int gm = m0 + r;
                float4 av = make_float4(0.f, 0.f, 0.f, 0.f);
                if (gm < INDIM)       av = *(const float4*)(W_emb + (size_t)gm * HH + k0 + c4);
                else if (gm == INDIM) av = *(const float4*)(b_emb + k0 + c4);
                As[c4 + 0][r] = av.x; As[c4 + 1][r] = av.y;
                As[c4 + 2][r] = av.z; As[c4 + 3][r] = av.w;
            }
        }
        {
            const int row = tid >> 4, c4 = (tid & 15) * 4;
            float4 bv = *(const float4*)(Wx0 + (size_t)(k0 + row) * HH + n0 + c4);
            *(float4*)(&Bs[row][c4]) = bv;
        }
        __syncthreads();
#pragma unroll
        for (int kk = 0; kk < 16; kk++) {
            float4 a0 = *(const float4*)(&As[kk][ty * 8]);
            float4 a1 = *(const float4*)(&As[kk][ty * 8 + 4]);
            float4 b4 = *(const float4*)(&Bs[kk][tx * 4]);
            float a[8] = {a0.x, a0.y, a0.z, a0.w, a1.x, a1.y, a1.z, a1.w};
            float b[4] = {b4.x, b4.y, b4.z, b4.w};
#pragma unroll
            for (int i = 0; i < 8; i++)
#pragma unroll
                for (int j = 0; j < 4; j++) acc[i][j] = fmaf(a[i], b[j], acc[i][j]);
        }
        __syncthreads();
    }
#pragma unroll
    for (int i = 0; i < 8; i++) {
        int gm = m0 + ty * 8 + i;
        int gn = n0 + tx * 4;
        if (gm < INDIM) {
#pragma unroll
            for (int j = 0; j < 4; j++) g_W0[(size_t)(d * INDIM + gm) * HH + gn + j] = acc[i][j];
        } else if (gm == INDIM) {
#pragma unroll
            for (int j = 0; j < 4; j++) g_b0[d * HH + gn + j] = acc[i][j] + bx0[gn + j];
        }
    }
}

// ---------- X0 = x @ W0 + b0 ----------
__global__ void x0_kernel(const float* __restrict__ x, const float* __restrict__ rx) {
    const int d = blockIdx.z;
    const float* A  = d ? rx : x;
    const float* Bw = g_W0 + (size_t)d * INDIM * HH;
    const int n0 = blockIdx.x * 64;
    const int m0 = blockIdx.y * 128;
    __shared__ float As[16][136];
    __shared__ float Bs[16][64];
    const int tid = threadIdx.x;
    const int ty = tid >> 4, tx = tid & 15;
    float acc[8][4];
#pragma unroll
    for (int i = 0; i < 8; i++)
#pragma unroll
        for (int j = 0; j < 4; j++) acc[i][j] = 0.f;

    for (int k0 = 0; k0 < INDIM; k0 += 16) {
        const bool full = (k0 + 16) <= INDIM;
        {
            const int row = tid >> 2, c4 = (tid & 3) * 4;
#pragma unroll
            for (int rr = 0; rr < 2; rr++) {
                int r = row + rr * 64;
                size_t gm = (size_t)(m0 + r);
                float4 av;
                if (full) {
                    av = *(const float4*)(A + gm * INDIM + k0 + c4);
                } else {
                    av.x = (k0 + c4 + 0 < INDIM) ? A[gm * INDIM + k0 + c4 + 0] : 0.f;
                    av.y = (k0 + c4 + 1 < INDIM) ? A[gm * INDIM + k0 + c4 + 1] : 0.f;
                    av.z = (k0 + c4 + 2 < INDIM) ? A[gm * INDIM + k0 + c4 + 2] : 0.f;
                    av.w = (k0 + c4 + 3 < INDIM) ? A[gm * INDIM + k0 + c4 + 3] : 0.f;
                }
                As[c4 + 0][r] = av.x; As[c4 + 1][r] = av.y;
                As[c4 + 2][r] = av.z; As[c4 + 3][r] = av.w;
            }
        }
        {
            const int row = tid >> 4, c4 = (tid & 15) * 4;
            float4 bv = make_float4(0.f, 0.f, 0.f, 0.f);
            if (k0 + row < INDIM) bv = *(const float4*)(Bw + (size_t)(k0 + row) * HH + n0 + c4);
            *(float4*)(&Bs[row][c4]) = bv;
        }
        __syncthreads();
#pragma unroll
        for (int kk = 0; kk < 16; kk++) {
            float4 a0 = *(const float4*)(&As[kk][ty * 8]);
            float4 a1 = *(const float4*)(&As[kk][ty * 8 + 4]);
            float4 b4 = *(const float4*)(&Bs[kk][tx * 4]);
            float a[8] = {a0.x, a0.y, a0.z, a0.w, a1.x, a1.y, a1.z, a1.w};
            float b[4] = {b4.x, b4.y, b4.z, b4.w};
#pragma unroll
            for (int i = 0; i < 8; i++)
#pragma unroll
                for (int j = 0; j < 4; j++) acc[i][j] = fmaf(a[i], b[j], acc[i][j]);
        }
        __syncthreads();
    }
#pragma unroll
    for (int i = 0; i < 8; i++) {
        int gm = m0 + ty * 8 + i;
        int bidx = gm >> 8;
        int t    = gm & 255;
        int gn = n0 + tx * 4;
        size_t base = ((size_t)(d * TT + t) * BB + bidx) * HH + gn;
#pragma unroll
        for (int j = 0; j < 4; j++) g_X0[base + j] = acc[i][j] + g_b0[d * HH + gn + j];
    }
}

// ---------- weights -> transposed bf16 hi/lo. mats/dir: 0=Wh0,1=Wx1,2=Wh1,3=Wx2,4=Wh2 ----------
__global__ void convw_kernel(const float* __restrict__ Wx_l2r, const float* __restrict__ Wh_l2r,
                             const float* __restrict__ Wx_r2l, const float* __restrict__ Wh_r2l) {
    const int mat = blockIdx.z;
    const int d = mat / 5, mm = mat % 5;
    const float* Wx = d ? Wx_r2l : Wx_l2r;
    const float* Wh = d ? Wh_r2l : Wh_l2r;
    const float* W;
    if      (mm == 0) W = Wh;
    else if (mm == 1) W = Wx + (size_t)1 * HH * HH;
    else if (mm == 2) W = Wh + (size_t)1 * HH * HH;
    else if (mm == 3) W = Wx + (size_t)2 * HH * HH;
    else              W = Wh + (size_t)2 * HH * HH;

    __shared__ float tile[32][33];
    const int k0 = blockIdx.y * 32, n0 = blockIdx.x * 32;
    for (int r = threadIdx.y; r < 32; r += 8)
        tile[r][threadIdx.x] = W[(size_t)(k0 + r) * HH + n0 + threadIdx.x];
    __syncthreads();
    for (int r = threadIdx.y; r < 32; r += 8) {
        float v = tile[threadIdx.x][r];     // W[k0+tx][n0+r]
        __nv_bfloat16 hi = __float2bfloat16(v);
        __nv_bfloat16 lo = __float2bfloat16(v - __bfloat162float(hi));
        size_t dst = ((size_t)mat * HH + n0 + r) * HH + k0 + threadIdx.x;
        g_Bh[dst] = hi;
        g_Bl[dst] = lo;
    }
}

// ---------- stage a 128-row x 256-col bf16 tile (row stride HH) into XOR-swizzled smem ----------
__device__ __forceinline__ void load_tile(uint32_t sm_dst, const __nv_bfloat16* __restrict__ src) {
    const int tid = threadIdx.x;
#pragma unroll
    for (int it = 0; it < 16; it++) {
        int idx = it * 256 + tid;
        int r = idx >> 5;
        int c = idx & 31;
        uint4 v = *(const uint4*)(src + (size_t)r * HH + c * 8);
        uint32_t dst = sm_dst + r * 512 + (((uint32_t)(c ^ (r & 7))) << 4);
        asm volatile("st.shared.v4.b32 [%0], {%1,%2,%3,%4};"
                     :: "r"(dst), "r"(v.x), "r"(v.y), "r"(v.z), "r"(v.w) : "memory");
    }
}

// ---------- single-B warp GEMM pass ----------
__device__ __forceinline__ void gemm_pass(uint32_t smA, uint32_t smB,
                                          const int aoff[2], const int aswz[2], int ahi,
                                          const int boff[4], const int bswz[4], int bhi,
                                          float acc[2][8][4]) {
#pragma unroll
    for (int mt = 0; mt < 2; mt++)
#pragma unroll
        for (int nt = 0; nt < 8; nt++)
#pragma unroll
            for (int i = 0; i < 4; i++) acc[mt][nt][i] = 0.f;
#pragma unroll 4
    for (int ks = 0; ks < 16; ks++) {
        uint32_t a[2][4];
#pragma unroll
        for (int mt = 0; mt < 2; mt++) {
            uint32_t addr = smA + aoff[mt] + ((uint32_t)((ks * 2 + ahi) ^ aswz[mt]) << 4);
            asm volatile("ldmatrix.sync.aligned.m8n8.x4.shared.b16 {%0,%1,%2,%3}, [%4];"
                         : "=r"(a[mt][0]), "=r"(a[mt][1]), "=r"(a[mt][2]), "=r"(a[mt][3])
                         : "r"(addr));
        }
        uint32_t bq[4][4];
#pragma unroll
        for (int np = 0; np < 4; np++) {
            uint32_t addr = smB + boff[np] + ((uint32_t)((ks * 2 + bhi) ^ bswz[np]) << 4);
            asm volatile("ldmatrix.sync.aligned.m8n8.x4.shared.b16 {%0,%1,%2,%3}, [%4];"
                         : "=r"(bq[np][0]), "=r"(bq[np][1]), "=r"(bq[np][2]), "=r"(bq[np][3])
                         : "r"(addr));
        }
#pragma unroll
        for (int mt = 0; mt < 2; mt++)
#pragma unroll
            for (int nt = 0; nt < 8; nt++) {
                uint32_t b0 = bq[nt >> 1][(nt & 1) ? 2 : 0];
                uint32_t b1 = bq[nt >> 1][(nt & 1) ? 3 : 1];
                asm volatile(
                    "mma.sync.aligned.m16n8k16.row.col.f32.bf16.bf16.f32 "
                    "{%0,%1,%2,%3}, {%4,%5,%6,%7}, {%8,%9}, {%0,%1,%2,%3};"
                    : "+f"(acc[mt][nt][0]), "+f"(acc[mt][nt][1]),
                      "+f"(acc[mt][nt][2]), "+f"(acc[mt][nt][3])
                    : "r"(a[mt][0]), "r"(a[mt][1]), "r"(a[mt][2]), "r"(a[mt][3]),
                      "r"(b0), "r"(b1));
            }
    }
}

// ---------- fused heavy pass: acc = A @ (B0 + B1)^T, A loaded once per ks ----------
__device__ __forceinline__ void gemm_heavy(uint32_t smA, uint32_t smB0, uint32_t smB1,
                                           const int aoff[2], const int aswz[2], int ahi,
                                           const int boff[4], const int bswz[4], int bhi,
                                           float acc[2][8][4]) {
#pragma unroll
    for (int mt = 0; mt < 2; mt++)
#pragma unroll
        for (int nt = 0; nt < 8; nt++)
#pragma unroll
            for (int i = 0; i < 4; i++) acc[mt][nt][i] = 0.f;
#pragma unroll 2
    for (int ks = 0; ks < 16; ks++) {
        uint32_t a[2][4];
#pragma unroll
        for (int mt = 0; mt < 2; mt++) {
            uint32_t addr = smA + aoff[mt] + ((uint32_t)((ks * 2 + ahi) ^ aswz[mt]) << 4);
            asm volatile("ldmatrix.sync.aligned.m8n8.x4.shared.b16 {%0,%1,%2,%3}, [%4];"
                         : "=r"(a[mt][0]), "=r"(a[mt][1]), "=r"(a[mt][2]), "=r"(a[mt][3])
                         : "r"(addr));
        }
#pragma unroll
        for (int half = 0; half < 2; half++) {
            uint32_t smB = half ? smB1 : smB0;
            uint32_t bq[4][4];
#pragma unroll
            for (int np = 0; np < 4; np++) {
                uint32_t addr = smB + boff[np] + ((uint32_t)((ks * 2 + bhi) ^ bswz[np]) << 4);
                asm volatile("ldmatrix.sync.aligned.m8n8.x4.shared.b16 {%0,%1,%2,%3}, [%4];"
                             : "=r"(bq[np][0]), "=r"(bq[np][1]), "=r"(bq[np][2]), "=r"(bq[np][3])
                             : "r"(addr));
            }
#pragma unroll
            for (int mt = 0; mt < 2; mt++)
#pragma unroll
                for (int nt = 0; nt < 8; nt++) {
                    uint32_t b0 = bq[nt >> 1][(nt & 1) ? 2 : 0];
                    uint32_t b1 = bq[nt >> 1][(nt & 1) ? 3 : 1];
                    asm volatile(
                        "mma.sync.aligned.m16n8k16.row.col.f32.bf16.bf16.f32 "
                        "{%0,%1,%2,%3}, {%4,%5,%6,%7}, {%8,%9}, {%0,%1,%2,%3};"
                        : "+f"(acc[mt][nt][0]), "+f"(acc[mt][nt][1]),
                          "+f"(acc[mt][nt][2]), "+f"(acc[mt][nt][3])
                        : "r"(a[mt][0]), "r"(a[mt][1]), "r"(a[mt][2]), "r"(a[mt][3]),
                          "r"(b0), "r"(b1));
                }
        }
    }
}

// ---------- persistent wavefront kernel ----------
__global__ void __launch_bounds__(256, 1)
persist_kernel(const float* __restrict__ ln_g, const float* __restrict__ ln_b) {
    extern __shared__ char smem_raw[];
    const uint32_t sbase = smem_u32(smem_raw);
    const int tid = threadIdx.x;
    const int wid = tid >> 5, lane = tid & 31;
    const int wm = wid & 3, wn = wid >> 2;
    __shared__ float redp[2][2][4];   // [row-half][s1/s2][warp]

    // per-lane ldmatrix address components
    int aoff[2], aswz[2];
#pragma unroll
    for (int mt = 0; mt < 2; mt++) {
        int r = wm * 32 + mt * 16 + (lane & 15);
        aoff[mt] = r * 512;
        aswz[mt] = r & 7;
    }
    const int ahi = lane >> 4;
    int boff[4], bswz[4];
#pragma unroll
    for (int np = 0; np < 4; np++) {
        int nl = wn * 64 + np * 16 + (lane & 7) + ((lane >> 4) << 3);
        boff[np] = nl * 512;
        bswz[np] = nl & 7;
    }
    const int bhi = (lane >> 3) & 1;

    auto decode = [](int tile, int& d, int& l, int& ntile, int& kc,
                     int& mat, int& asrc, int& koff) {
        d = tile / 40;
        int r = tile % 40;
        if (r < 8)       { l = 0; ntile = r >> 1;        kc = r & 1; }
        else if (r < 24) { l = 1; ntile = (r - 8) >> 2;  kc = (r - 8) & 3; }
        else             { l = 2; ntile = (r - 24) >> 2; kc = (r - 24) & 3; }
        if (l == 0)      { mat = d * 5 + 0;         asrc = 0;     koff = kc * 256; }
        else if (kc < 2) { mat = d * 5 + 2 * l - 1; asrc = l - 1; koff = kc * 256; }
        else             { mat = d * 5 + 2 * l;     asrc = l;     koff = (kc - 2) * 256; }
    };

    // work setup
    const int cta = blockIdx.x;
    const bool heavy = (cta < NTILES);
    const __nv_bfloat16* pA[2] = {nullptr, nullptr};
    uint32_t pB[2] = {0, 0};
    float* pDst[2] = {nullptr, nullptr};
    int pL[2] = {0, 0};
    int npass = 0;

    if (heavy) {
        int d, l, ntile, kc, mat, asrc, koff;
        decode(cta, d, l, ntile, kc, mat, asrc, koff);
        int n0 = ntile * 128;
        load_tile(sbase + SM_B0, g_Bh + ((size_t)mat * HH + n0) * HH + koff);
        load_tile(sbase + SM_B1, g_Bl + ((size_t)mat * HH + n0) * HH + koff);
        pA[0]   = g_hh + (size_t)(d * 3 + asrc) * BB * HH + koff;
        pDst[0] = g_pp + (size_t)((d * 3 + l) * 8 + kc * 2 + 0) * (BB * HH) + n0;
        pL[0]   = l;
        npass = 1;
    } else {
        int j = cta - NTILES;
        int units[2] = {j, (j < 12) ? (68 + j) : -1};
        for (int q = 0; q < 2; q++) {
            if (units[q] < 0) break;
            int d, l, ntile, kc, mat, asrc, koff;
            decode(units[q], d, l, ntile, kc, mat, asrc, koff);
            int n0 = ntile * 128;
            uint32_t sb = sbase + (q ? SM_B1 : SM_B0);
            load_tile(sb, g_Bh + ((size_t)mat * HH + n0) * HH + koff);
            pA[q]   = g_hl + (size_t)(d * 3 + asrc) * BB * HH + koff;
            pB[q]   = sb;
            pDst[q] = g_pp + (size_t)((d * 3 + l) * 8 + kc * 2 + 1) * (BB * HH) + n0;
            pL[q]   = l;
            npass = q + 1;
        }
    }
    __syncthreads();

    // epilogue store lane mapping
    const int er = lane >> 2, ec = (lane & 3) * 2;
    // LN lane mapping: 2 rows per CTA, 128 threads per row
    const int rhalf = tid >> 7;
    const int tl = tid & 127;
    const int lnwarp = (tid >> 5) & 3;
    const int lj = tl * 4;

    float acc[2][8][4];
    unsigned bt = 0;

    for (int s = 0; s < NSTEPS; s++) {
        // ================= GEMM phase =================
        if (heavy) {
            const int t = s - pL[0];
            if (t >= 0 && t < TT) {
                __syncthreads();
                load_tile(sbase + SM_A, pA[0]);
                __syncthreads();
                gemm_heavy(sbase + SM_A, sbase + SM_B0, sbase + SM_B1,
                           aoff, aswz, ahi, boff, bswz, bhi, acc);
                float* dst = pDst[0];
#pragma unroll
                for (int mt = 0; mt < 2; mt++) {
                    int row0 = wm * 32 + mt * 16 + er;
#pragma unroll
                    for (int nt = 0; nt < 8; nt++) {
                        int col = wn * 64 + nt * 8 + ec;
                        *(float2*)(dst + (size_t)row0 * HH + col) =
                            make_float2(acc[mt][nt][0], acc[mt][nt][1]);
                        *(float2*)(dst + (size_t)(row0 + 8) * HH + col) =
                            make_float2(acc[mt][nt][2], acc[mt][nt][3]);
                    }
                }
            }
        } else {
            for (int p = 0; p < npass; p++) {
                const int t = s - pL[p];
                if (t < 0 || t >= TT) continue;
                __syncthreads();
                load_tile(sbase + SM_A, pA[p]);
                __syncthreads();
                gemm_pass(sbase + SM_A, pB[p], aoff, aswz, ahi, boff, bswz, bhi, acc);
                float* dst = pDst[p];
#pragma unroll
                for (int mt = 0; mt < 2; mt++) {
                    int row0 = wm * 32 + mt * 16 + er;
#pragma unroll
                    for (int nt = 0; nt < 8; nt++) {
                        int col = wn * 64 + nt * 8 + ec;
                        *(float2*)(dst + (size_t)row0 * HH + col) =
                            make_float2(acc[mt][nt][0], acc[mt][nt][1]);
                        *(float2*)(dst + (size_t)(row0 + 8) * HH + col) =
                            make_float2(acc[mt][nt][2], acc[mt][nt][3]);
                    }
                }
            }
        }

        gsync(++bt);

        // ================= LN + tanh phase: 2 rows per CTA per batch =================
#pragma unroll 1
        for (int it = 0; it < 3; it++) {
            const int base = it * 296 + (blockIdx.x << 1);
            if (base >= 768) break;                 // uniform across CTA
            const int row = base + rhalf;
            const int task = row >> 7, b = row & 127;
            const int dd = task / 3, ll = task - dd * 3;
            const int tt2 = s - ll;
            const bool rvalid = (tt2 >= 0 && tt2 < TT);

            float4 v = make_float4(0.f, 0.f, 0.f, 0.f);
            if (rvalid) {
                const float* ppb = g_pp + (size_t)(dd * 3 + ll) * 8 * (BB * HH)
                                        + (size_t)b * HH + lj;
                float4 cb = *(const float4*)(g_cb + task * HH + lj);
                if (ll == 0) {
                    float4 x0 = *(const float4*)(g_X0 + ((size_t)(dd * TT + tt2) * BB + b) * HH + lj);
                    float4 p[4];
#pragma unroll
                    for (int c = 0; c < 4; c++)
                        p[c] = *(const float4*)(ppb + (size_t)c * (BB * HH));
                    v.x = cb.x + x0.x + p[0].x + p[1].x + p[2].x + p[3].x;
                    v.y = cb.y + x0.y + p[0].y + p[1].y + p[2].y + p[3].y;
                    v.z = cb.z + x0.z + p[0].z + p[1].z + p[2].z + p[3].z;
                    v.w = cb.w + x0.w + p[0].w + p[1].w + p[2].w + p[3].w;
                } else {
                    float4 p[8];
#pragma unroll
                    for (int c = 0; c < 8; c++)
                        p[c] = *(const float4*)(ppb + (size_t)c * (BB * HH));
                    v.x = cb.x + p[0].x + p[1].x + p[2].x + p[3].x + p[4].x + p[5].x + p[6].x + p[7].x;
                    v.y = cb.y + p[0].y + p[1].y + p[2].y + p[3].y + p[4].y + p[5].y + p[6].y + p[7].y;
                    v.z = cb.z + p[0].z + p[1].z + p[2].z + p[3].z + p[4].z + p[5].z + p[6].z + p[7].z;
                    v.w = cb.w + p[0].w + p[1].w + p[2].w + p[3].w + p[4].w + p[5].w + p[6].w + p[7].w;
                }
            }
            float s1 = v.x + v.y + v.z + v.w;
            float s2 = v.x * v.x + v.y * v.y + v.z * v.z + v.w * v.w;
#pragma unroll
            for (int o = 16; o > 0; o >>= 1) {
                s1 += __shfl_xor_sync(0xffffffffu, s1, o);
                s2 += __shfl_xor_sync(0xffffffffu, s2, o);
            }
            if (lane == 0) { redp[rhalf][0][lnwarp] = s1; redp[rhalf][1][lnwarp] = s2; }
            __syncthreads();
            if (rvalid) {
                float t1 = redp[rhalf][0][0] + redp[rhalf][0][1] + redp[rhalf][0][2] + redp[rhalf][0][3];
                float t2 = redp[rhalf][1][0] + redp[rhalf][1][1] + redp[rhalf][1][2] + redp[rhalf][1][3];
                const float mean = t1 * (1.f / HH);
                const float var  = t2 * (1.f / HH) - mean * mean;
                const float inv  = rsqrtf(var + LNEPS);
                float4 g4 = *(const float4*)(ln_g + ll * HH + lj);
                float4 b4 = *(const float4*)(ln_b + ll * HH + lj);
                float h0 = tanhf((v.x - mean) * inv * g4.x + b4.x);
                float h1 = tanhf((v.y - mean) * inv * g4.y + b4.y);
                float h2 = tanhf((v.z - mean) * inv * g4.z + b4.z);
                float h3 = tanhf((v.w - mean) * inv * g4.w + b4.w);
                size_t hidx = (size_t)(dd * 3 + ll) * BB * HH + (size_t)b * HH + lj;
                __nv_bfloat162 hh01 = __floats2bfloat162_rn(h0, h1);
                __nv_bfloat162 hh23 = __floats2bfloat162_rn(h2, h3);
                uint2 uh;
                uh.x = *(uint32_t*)&hh01;
                uh.y = *(uint32_t*)&hh23;
                *(uint2*)(g_hh + hidx) = uh;
                float l0f = h0 - __bfloat162float(__float2bfloat16(h0));
                float l1f = h1 - __bfloat162float(__float2bfloat16(h1));
                float l2f = h2 - __bfloat162float(__float2bfloat16(h2));
                float l3f = h3 - __bfloat162float(__float2bfloat16(h3));
                __nv_bfloat162 hl01 = __floats2bfloat162_rn(l0f, l1f);
                __nv_bfloat162 hl23 = __floats2bfloat162_rn(l2f, l3f);
                uint2 ul;
                ul.x = *(uint32_t*)&hl01;
                ul.y = *(uint32_t*)&hl23;
                *(uint2*)(g_hl + hidx) = ul;
                if (ll == 2)
                    *(float4*)(g_o2 + ((size_t)(dd * TT + tt2) * BB + b) * HH + lj) =
                        make_float4(h0, h1, h2, h3);
            }
            __syncthreads();
        }

        gsync(++bt);
    }
}

// ---------- gather + concat + FC ----------
__global__ void final_kernel(const int* __restrict__ pad,
                             const float* __restrict__ W_fc, const float* __restrict__ b_fc,
                             float* __restrict__ out) {
    __shared__ float cs[4][1024];
    const int sub  = threadIdx.x >> 6;
    const int lane = threadIdx.x & 63;
    const int r = blockIdx.x * 4 + sub;
    const int b = r >> 8;
    const int t = r & 255;
    const int p = pad[b];
    const int tt = (t < p) ? (p - t - 1) : t;
    const float* a0 = g_o2 + ((size_t)(0 * TT + t)  * BB + b) * HH;
    const float* a1 = g_o2 + ((size_t)(1 * TT + tt) * BB + b) * HH;
#pragma unroll
    for (int i = 0; i < 4; i++) {
        int j = lane * 4 + i * 256;
        float4 vv = (j < 512) ? *(const float4*)(a0 + j) : *(const float4*)(a1 + j - 512);
        *(float4*)(&cs[sub][j]) = vv;
    }
    __syncthreads();
    if (lane < NCLS) {
        float acc = b_fc[lane];
#pragma unroll 8
        for (int k = 0; k < 1024; k++) acc = fmaf(cs[sub][k], W_fc[k * NCLS + lane], acc);
        out[(size_t)r * NCLS + lane] = acc;
    }
}

// ---------- host launcher ----------
extern "C" void kernel_launch(void* const* d_in, const int* in_sizes, int n_in,
                              void* d_out, int out_size) {
    (void)in_sizes; (void)n_in; (void)out_size;
    const float* x      = (const float*)d_in[0];
    const float* rx     = (const float*)d_in[1];
    const int*   pad    = (const int*)  d_in[2];
    const float* W_emb  = (const float*)d_in[4];
    const float* b_emb  = (const float*)d_in[5];
    const float* Wx_l2r = (const float*)d_in[6];
    const float* bx_l2r = (const float*)d_in[7];
    const float* Wh_l2r = (const float*)d_in[8];
    const float* bh_l2r = (const float*)d_in[9];
    const float* Wx_r2l = (const float*)d_in[10];
    const float* bx_r2l = (const float*)d_in[11];
    const float* Wh_r2l = (const float*)d_in[12];
    const float* bh_r2l = (const float*)d_in[13];
    const float* ln_g   = (const float*)d_in[14];
    const float* ln_b   = (const float*)d_in[15];
    const float* W_fc   = (const float*)d_in[16];
    const float* b_fc   = (const float*)d_in[17];
    float* out = (float*)d_out;

    static int attr_done = 0;
    if (!attr_done) {
        cudaFuncSetAttribute(persist_kernel, cudaFuncAttributeMaxDynamicSharedMemorySize, DSMEM);
        attr_done = 1;
    }

    init_kernel<<<(2 * 3 * BB * HH + 255) / 256, 256>>>(bx_l2r, bh_l2r, bx_r2l, bh_r2l);
    w0_kernel<<<dim3(8, 3, 2), 256>>>(W_emb, b_emb, Wx_l2r, bx_l2r, Wx_r2l, bx_r2l);
    x0_kernel<<<dim3(8, 256, 2), 256>>>(x, rx);
    convw_kernel<<<dim3(16, 16, 10), dim3(32, 8)>>>(Wx_l2r, Wh_l2r, Wx_r2l, Wh_r2l);

    persist_kernel<<<GRID_P, 256, DSMEM>>>(ln_g, ln_b);

    final_kernel<<<8192, 256>>>(pad, W_fc, b_fc, out);
}

// round 7
// speedup vs baseline: 1.9329x; 1.2116x over previous
#include <cuda_runtime.h>
#include <cuda_fp16.h>
#include <math.h>
#include <stdint.h>

#define BB    128
#define TT    256
#define INDIM 300
#define HH    512
#define NCLS  45
#define LNEPS 1e-5f

#define GRID_P  148
#define NSTEPS  258

// persist smem layout (byte offsets)
#define SM_BH   0
#define SM_BL   32768
#define SM_A    65536
#define SM_SBH  98304
#define SM_SBL  106496
#define SM_A2   114688
#define DSMEM   147456

// x0mma smem layout
#define X0_AH  0
#define X0_AL  16384
#define X0_BH  32768
#define X0_BL  49152
#define X0_DS  65536

// ---------- device scratch ----------
__device__ float g_W0[2 * INDIM * HH];
__device__ float g_b0[2 * HH];
__device__ __align__(16) __half g_W0h[2 * HH * 320];        // [d][n][k320]
__device__ __align__(16) __half g_W0l[2 * HH * 320];
__device__ __align__(16) __half g_Xh[2 * 32768 * 320];      // [d][m][k320]
__device__ __align__(16) __half g_Xl[2 * 32768 * 320];
__device__ float g_X0[2 * TT * BB * HH];
__device__ __align__(16) __half g_Bh[10 * HH * HH];         // [mat][n][k512] hi
__device__ __align__(16) __half g_Bl[10 * HH * HH];         // lo
__device__ __align__(16) __half g_hh[2 * 3 * BB * HH];      // h fp16
__device__ float g_pp[2 * 3 * 8 * BB * HH];                 // slots (d*3+l)*8+kc
__device__ float g_o2[2 * TT * BB * HH];
__device__ float g_cb[6 * HH];
__device__ unsigned g_barc;
__device__ unsigned g_sense;

// ---------- helpers ----------
__device__ __forceinline__ uint32_t smem_u32(const void* p) {
    uint32_t a;
    asm("{ .reg .u64 t; cvta.to.shared.u64 t, %1; cvt.u32.u64 %0, t; }" : "=r"(a) : "l"(p));
    return a;
}

__device__ __forceinline__ void gsync(unsigned target) {
    __syncthreads();
    if (threadIdx.x == 0) {
        unsigned old;
        asm volatile("atom.add.acq_rel.gpu.u32 %0, [%1], 1;" : "=r"(old) : "l"(&g_barc) : "memory");
        if (old == (unsigned)(GRID_P - 1)) {
            asm volatile("st.relaxed.gpu.u32 [%0], 0;" :: "l"(&g_barc) : "memory");
            asm volatile("st.release.gpu.u32 [%0], %1;" :: "l"(&g_sense), "r"(target) : "memory");
        } else {
            unsigned sv;
            do {
                asm volatile("ld.acquire.gpu.u32 %0, [%1];" : "=r"(sv) : "l"(&g_sense) : "memory");
            } while (sv != target);
        }
        __threadfence();
    }
    __syncthreads();
}

// ---------- init ----------
__global__ void init_kernel(const float* __restrict__ bx_l2r, const float* __restrict__ bh_l2r,
                            const float* __restrict__ bx_r2l, const float* __restrict__ bh_r2l) {
    int i = blockIdx.x * blockDim.x + threadIdx.x;
    if (i == 0) { g_barc = 0; g_sense = 0; }
    if (i < 2 * 3 * BB * HH) g_hh[i] = __float2half(0.f);
    if (i < 6 * HH) {
        int task = i / HH, j = i % HH;
        int dd = task / 3, ll = task - dd * 3;
        const float* bx = dd ? bx_r2l : bx_l2r;
        const float* bh = dd ? bh_r2l : bh_l2r;
        float cb = bh[ll * HH + j];
        if (ll != 0) cb += bx[ll * HH + j];
        g_cb[i] = cb;
    }
}

// ---------- W0 = [W_emb; b_emb] @ Wx0 (+bx0), fp32 ----------
__global__ void w0_kernel(const float* __restrict__ W_emb, const float* __restrict__ b_emb,
                          const float* __restrict__ Wx_l2r, const float* __restrict__ bx_l2r,
                          const float* __restrict__ Wx_r2l, const float* __restrict__ bx_r2l) {
    const int d = blockIdx.z;
    const float* Wx0 = d ? Wx_r2l : Wx_l2r;
    const float* bx0 = d ? bx_r2l : bx_l2r;
    const int n0 = blockIdx.x * 64;
    const int m0 = blockIdx.y * 128;
    __shared__ float As[16][136];
    __shared__ float Bs[16][64];
    const int tid = threadIdx.x;
    const int ty = tid >> 4, tx = tid & 15;
    float acc[8][4];
#pragma unroll
    for (int i = 0; i < 8; i++)
#pragma unroll
        for (int j = 0; j < 4; j++) acc[i][j] = 0.f;

    for (int k0 = 0; k0 < HH; k0 += 16) {
        {
            const int row = tid >> 2, c4 = (tid & 3) * 4;
#pragma unroll
            for (int rr = 0; rr < 2; rr++) {
                int r = row + rr * 64;
                int gm = m0 + r;
                float4 av = make_float4(0.f, 0.f, 0.f, 0.f);
                if (gm < INDIM)       av = *(const float4*)(W_emb + (size_t)gm * HH + k0 + c4);
                else if (gm == INDIM) av = *(const float4*)(b_emb + k0 + c4);
                As[c4 + 0][r] = av.x; As[c4 + 1][r] = av.y;
                As[c4 + 2][r] = av.z; As[c4 + 3][r] = av.w;
            }
        }
        {
            const int row = tid >> 4, c4 = (tid & 15) * 4;
            float4 bv = *(const float4*)(Wx0 + (size_t)(k0 + row) * HH + n0 + c4);
            *(float4*)(&Bs[row][c4]) = bv;
        }
        __syncthreads();
#pragma unroll
        for (int kk = 0; kk < 16; kk++) {
            float4 a0 = *(const float4*)(&As[kk][ty * 8]);
            float4 a1 = *(const float4*)(&As[kk][ty * 8 + 4]);
            float4 b4 = *(const float4*)(&Bs[kk][tx * 4]);
            float a[8] = {a0.x, a0.y, a0.z, a0.w, a1.x, a1.y, a1.z, a1.w};
            float b[4] = {b4.x, b4.y, b4.z, b4.w};
#pragma unroll
            for (int i = 0; i < 8; i++)
#pragma unroll
                for (int j = 0; j < 4; j++) acc[i][j] = fmaf(a[i], b[j], acc[i][j]);
        }
        __syncthreads();
    }
#pragma unroll
    for (int i = 0; i < 8; i++) {
        int gm = m0 + ty * 8 + i;
        int gn = n0 + tx * 4;
        if (gm < INDIM) {
#pragma unroll
            for (int j = 0; j < 4; j++) g_W0[(size_t)(d * INDIM + gm) * HH + gn + j] = acc[i][j];
        } else if (gm == INDIM) {
#pragma unroll
            for (int j = 0; j < 4; j++) g_b0[d * HH + gn + j] = acc[i][j] + bx0[gn + j];
        }
    }
}

// ---------- W0 fp32 [d][k300][n] -> fp16 hi/lo transposed [d][n][k320] ----------
__global__ void w0conv_kernel() {
    __shared__ float tile[32][33];
    const int d = blockIdx.z;
    const int k0 = blockIdx.y * 32, n0 = blockIdx.x * 32;
    const int tx = threadIdx.x;
    for (int r = threadIdx.y; r < 32; r += 8) {
        int k = k0 + r;
        tile[r][tx] = (k < INDIM) ? g_W0[(size_t)(d * INDIM + k) * HH + n0 + tx] : 0.f;
    }
    __syncthreads();
    for (int r = threadIdx.y; r < 32; r += 8) {
        float v = tile[tx][r];            // W0[k0+tx][n0+r]
        __half hi = __float2half(v);
        __half lo = __float2half(v - __half2float(hi));
        size_t dst = ((size_t)d * HH + n0 + r) * 320 + k0 + tx;
        g_W0h[dst] = hi;
        g_W0l[dst] = lo;
    }
}

// ---------- x/rx -> fp16 hi/lo, K padded to 320 ----------
__global__ void xconv_kernel(const float* __restrict__ x, const float* __restrict__ rx) {
    const int m = blockIdx.x & 32767;
    const int d = blockIdx.x >> 15;
    const float* src = d ? rx : x;
    const int c = threadIdx.x;
    float v = (c < INDIM) ? src[(size_t)m * INDIM + c] : 0.f;
    __half h = __float2half(v);
    size_t dst = (size_t)blockIdx.x * 320 + c;
    g_Xh[dst] = h;
    g_Xl[dst] = __float2half(v - __half2float(h));
}

// ---------- weights -> transposed fp16 hi/lo. mats/dir: 0=Wh0,1=Wx1,2=Wh1,3=Wx2,4=Wh2 ----------
__global__ void convw_kernel(const float* __restrict__ Wx_l2r, const float* __restrict__ Wh_l2r,
                             const float* __restrict__ Wx_r2l, const float* __restrict__ Wh_r2l) {
    const int mat = blockIdx.z;
    const int d = mat / 5, mm = mat % 5;
    const float* Wx = d ? Wx_r2l : Wx_l2r;
    const float* Wh = d ? Wh_r2l : Wh_l2r;
    const float* W;
    if      (mm == 0) W = Wh;
    else if (mm == 1) W = Wx + (size_t)1 * HH * HH;
    else if (mm == 2) W = Wh + (size_t)1 * HH * HH;
    else if (mm == 3) W = Wx + (size_t)2 * HH * HH;
    else              W = Wh + (size_t)2 * HH * HH;

    __shared__ float tile[32][33];
    const int k0 = blockIdx.y * 32, n0 = blockIdx.x * 32;
    for (int r = threadIdx.y; r < 32; r += 8)
        tile[r][threadIdx.x] = W[(size_t)(k0 + r) * HH + n0 + threadIdx.x];
    __syncthreads();
    for (int r = threadIdx.y; r < 32; r += 8) {
        float v = tile[threadIdx.x][r];   // W[k0+tx][n0+r]
        __half hi = __float2half(v);
        __half lo = __float2half(v - __half2float(hi));
        size_t dst = ((size_t)mat * HH + n0 + r) * HH + k0 + threadIdx.x;
        g_Bh[dst] = hi;
        g_Bl[dst] = lo;
    }
}

// ---------- loaders: tiles with 16B-chunk XOR swizzle ----------
// 128 rows x 128 halfs (256B/row), src row stride 512 halfs
__device__ __forceinline__ void load_t128(uint32_t dst, const __half* __restrict__ src) {
    const int tid = threadIdx.x;
#pragma unroll
    for (int it = 0; it < 8; it++) {
        int idx = it * 256 + tid;
        int r = idx >> 4, c = idx & 15;
        uint4 v = *(const uint4*)(src + (size_t)r * 512 + c * 8);
        uint32_t a = dst + r * 256 + (((uint32_t)(c ^ (r & 7))) << 4);
        asm volatile("st.shared.v4.b32 [%0], {%1,%2,%3,%4};"
                     :: "r"(a), "r"(v.x), "r"(v.y), "r"(v.z), "r"(v.w) : "memory");
    }
}
// 32 rows x 128 halfs
__device__ __forceinline__ void load_t32(uint32_t dst, const __half* __restrict__ src) {
    const int tid = threadIdx.x;
#pragma unroll
    for (int it = 0; it < 2; it++) {
        int idx = it * 256 + tid;
        int r = idx >> 4, c = idx & 15;
        uint4 v = *(const uint4*)(src + (size_t)r * 512 + c * 8);
        uint32_t a = dst + r * 256 + (((uint32_t)(c ^ (r & 7))) << 4);
        asm volatile("st.shared.v4.b32 [%0], {%1,%2,%3,%4};"
                     :: "r"(a), "r"(v.x), "r"(v.y), "r"(v.z), "r"(v.w) : "memory");
    }
}
// 128 rows x 64 halfs (128B/row), src row stride 320 halfs
__device__ __forceinline__ void load_t64(uint32_t dst, const __half* __restrict__ src) {
    const int tid = threadIdx.x;
#pragma unroll
    for (int it = 0; it < 4; it++) {
        int idx = it * 256 + tid;
        int r = idx >> 3, c = idx & 7;
        uint4 v = *(const uint4*)(src + (size_t)r * 320 + c * 8);
        uint32_t a = dst + r * 128 + (((uint32_t)(c ^ (r & 7))) << 4);
        asm volatile("st.shared.v4.b32 [%0], {%1,%2,%3,%4};"
                     :: "r"(a), "r"(v.x), "r"(v.y), "r"(v.z), "r"(v.w) : "memory");
    }
}

#define MMA_F16(acc, a0, a1, a2, a3, b0, b1) \
    asm volatile( \
        "mma.sync.aligned.m16n8k16.row.col.f32.f16.f16.f32 " \
        "{%0,%1,%2,%3}, {%4,%5,%6,%7}, {%8,%9}, {%0,%1,%2,%3};" \
        : "+f"((acc)[0]), "+f"((acc)[1]), "+f"((acc)[2]), "+f"((acc)[3]) \
        : "r"(a0), "r"(a1), "r"(a2), "r"(a3), "r"(b0), "r"(b1))

#define LDSM4(r0, r1, r2, r3, addr) \
    asm volatile("ldmatrix.sync.aligned.m8n8.x4.shared.b16 {%0,%1,%2,%3}, [%4];" \
                 : "=r"(r0), "=r"(r1), "=r"(r2), "=r"(r3) : "r"(addr))

// ---------- main fused GEMM: acc = A(128x128) @ (Bh+Bl)(128n x 128k)^T ----------
__device__ __forceinline__ void gemm_main(uint32_t smA, uint32_t smBh, uint32_t smBl,
                                          const int aoff[2], const int aswz[2], int ahi,
                                          const int boff[4], const int bswz[4], int bhi,
                                          float acc[2][8][4]) {
#pragma unroll
    for (int mt = 0; mt < 2; mt++)
#pragma unroll
        for (int nt = 0; nt < 8; nt++)
#pragma unroll
            for (int i = 0; i < 4; i++) acc[mt][nt][i] = 0.f;
#pragma unroll 2
    for (int ks = 0; ks < 8; ks++) {
        uint32_t a[2][4];
#pragma unroll
        for (int mt = 0; mt < 2; mt++) {
            uint32_t addr = smA + aoff[mt] + ((uint32_t)((ks * 2 + ahi) ^ aswz[mt]) << 4);
            LDSM4(a[mt][0], a[mt][1], a[mt][2], a[mt][3], addr);
        }
#pragma unroll
        for (int half = 0; half < 2; half++) {
            uint32_t smB = half ? smBl : smBh;
            uint32_t bq[4][4];
#pragma unroll
            for (int np = 0; np < 4; np++) {
                uint32_t addr = smB + boff[np] + ((uint32_t)((ks * 2 + bhi) ^ bswz[np]) << 4);
                LDSM4(bq[np][0], bq[np][1], bq[np][2], bq[np][3], addr);
            }
#pragma unroll
            for (int mt = 0; mt < 2; mt++)
#pragma unroll
                for (int nt = 0; nt < 8; nt++) {
                    uint32_t b0 = bq[nt >> 1][(nt & 1) ? 2 : 0];
                    uint32_t b1 = bq[nt >> 1][(nt & 1) ? 3 : 1];
                    MMA_F16(acc[mt][nt], a[mt][0], a[mt][1], a[mt][2], a[mt][3], b0, b1);
                }
        }
    }
}

// ---------- persistent wavefront kernel ----------
__global__ void __launch_bounds__(256, 1)
persist_kernel(const float* __restrict__ ln_g, const float* __restrict__ ln_b) {
    extern __shared__ char smem_raw[];
    const uint32_t sbase = smem_u32(smem_raw);
    const int tid = threadIdx.x;
    const int wid = tid >> 5, lane = tid & 31;
    const int wm = wid & 3, wn = wid >> 2;
    __shared__ float redp[2][2][4];

    // main-unit ldmatrix lane components (256B-row tiles)
    int aoff[2], aswz[2];
#pragma unroll
    for (int mt = 0; mt < 2; mt++) {
        int r = wm * 32 + mt * 16 + (lane & 15);
        aoff[mt] = r * 256;
        aswz[mt] = r & 7;
    }
    const int ahi = lane >> 4;
    int boff[4], bswz[4];
#pragma unroll
    for (int np = 0; np < 4; np++) {
        int nl = wn * 64 + np * 16 + (lane & 7) + ((lane >> 4) << 3);
        boff[np] = nl * 256;
        bswz[np] = nl & 7;
    }
    const int bhi = (lane >> 3) & 1;

    // unit decode: u in 0..159 -> (d,l,ntile,kc,mat,asrc,koff,slot)
    auto decode = [](int u, int& d, int& l, int& ntile, int& kc, int& mat, int& asrc) {
        d = u / 80;
        int r = u % 80;
        if (r < 16)      { l = 0; ntile = r >> 2;        kc = r & 3;
                           mat = d * 5 + 0; asrc = 0; }
        else if (r < 48) { l = 1; int rr = r - 16; ntile = rr >> 3; kc = rr & 7;
                           if (kc < 4) { mat = d * 5 + 1; asrc = 0; }
                           else        { mat = d * 5 + 2; asrc = 1; } }
        else             { l = 2; int rr = r - 48; ntile = rr >> 3; kc = rr & 7;
                           if (kc < 4) { mat = d * 5 + 3; asrc = 1; }
                           else        { mat = d * 5 + 4; asrc = 2; } }
    };

    const int cta = blockIdx.x;
    // main unit (all 148 CTAs)
    int dM, lM, ntM, kcM, matM, asM;
    decode(cta, dM, lM, ntM, kcM, matM, asM);
    const int koffM = (kcM & 3) * 128;
    const int n0M = ntM * 128;
    const __half* Amain = g_hh + (size_t)(dM * 3 + asM) * BB * HH + koffM;
    float* dstM = g_pp + (size_t)((dM * 3 + lM) * 8 + kcM) * (BB * HH) + n0M;
    load_t128(sbase + SM_BH, g_Bh + ((size_t)matM * HH + n0M) * HH + koffM);
    load_t128(sbase + SM_BL, g_Bl + ((size_t)matM * HH + n0M) * HH + koffM);

    // sub unit (CTAs 0..47): N=32 slice of units 148..159
    const bool hasSub = (cta < 48);
    int lS = 0;
    const __half* Asub = nullptr;
    float* dstS = nullptr;
    if (hasSub) {
        int su = 148 + (cta >> 2);
        int nsub = cta & 3;
        int dS, ntS, kcS, matS, asS;
        decode(su, dS, lS, ntS, kcS, matS, asS);
        int koffS = (kcS & 3) * 128;
        int n0S = ntS * 128 + nsub * 32;
        Asub = g_hh + (size_t)(dS * 3 + asS) * BB * HH + koffS;
        dstS = g_pp + (size_t)((dS * 3 + lS) * 8 + kcS) * (BB * HH) + n0S;
        load_t32(sbase + SM_SBH, g_Bh + ((size_t)matS * HH + n0S) * HH + koffS);
        load_t32(sbase + SM_SBL, g_Bl + ((size_t)matS * HH + n0S) * HH + koffS);
    }
    __syncthreads();

    const int er = lane >> 2, ec = (lane & 3) * 2;
    // sub-unit lane components
    const int ar2 = (wid << 4) + (lane & 15);
    const int aoff2 = ar2 * 256, aswz2 = ar2 & 7;
    int boff2[2], bswz2[2];
#pragma unroll
    for (int np = 0; np < 2; np++) {
        int nl = np * 16 + (lane & 7) + ((lane >> 4) << 3);
        boff2[np] = nl * 256;
        bswz2[np] = nl & 7;
    }
    // LN lane mapping
    const int rhalf = tid >> 7;
    const int tl = tid & 127;
    const int lnwarp = (tid >> 5) & 3;
    const int lj = tl * 4;

    float acc[2][8][4];
    unsigned bt = 0;

    for (int s = 0; s < NSTEPS; s++) {
        const int tM = s - lM;
        const bool runM = (tM >= 0 && tM < TT);
        const int tS = s - lS;
        const bool runS = hasSub && (tS >= 0 && tS < TT);

        __syncthreads();
        if (runM) load_t128(sbase + SM_A, Amain);
        if (runS) load_t128(sbase + SM_A2, Asub);
        __syncthreads();

        if (runM) {
            gemm_main(sbase + SM_A, sbase + SM_BH, sbase + SM_BL,
                      aoff, aswz, ahi, boff, bswz, bhi, acc);
#pragma unroll
            for (int mt = 0; mt < 2; mt++) {
                int row0 = wm * 32 + mt * 16 + er;
#pragma unroll
                for (int nt = 0; nt < 8; nt++) {
                    int col = wn * 64 + nt * 8 + ec;
                    *(float2*)(dstM + (size_t)row0 * HH + col) =
                        make_float2(acc[mt][nt][0], acc[mt][nt][1]);
                    *(float2*)(dstM + (size_t)(row0 + 8) * HH + col) =
                        make_float2(acc[mt][nt][2], acc[mt][nt][3]);
                }
            }
        }
        if (runS) {
            float accs[4][4];
#pragma unroll
            for (int nt = 0; nt < 4; nt++)
#pragma unroll
                for (int i = 0; i < 4; i++) accs[nt][i] = 0.f;
#pragma unroll 2
            for (int ks = 0; ks < 8; ks++) {
                uint32_t a2[4];
                uint32_t addr = sbase + SM_A2 + aoff2 + ((uint32_t)((ks * 2 + ahi) ^ aswz2) << 4);
                LDSM4(a2[0], a2[1], a2[2], a2[3], addr);
#pragma unroll
                for (int half = 0; half < 2; half++) {
                    uint32_t smB = sbase + (half ? SM_SBL : SM_SBH);
                    uint32_t bq[2][4];
#pragma unroll
                    for (int np = 0; np < 2; np++) {
                        uint32_t ba = smB + boff2[np] + ((uint32_t)((ks * 2 + bhi) ^ bswz2[np]) << 4);
                        LDSM4(bq[np][0], bq[np][1], bq[np][2], bq[np][3], ba);
                    }
#pragma unroll
                    for (int nt = 0; nt < 4; nt++) {
                        uint32_t b0 = bq[nt >> 1][(nt & 1) ? 2 : 0];
                        uint32_t b1 = bq[nt >> 1][(nt & 1) ? 3 : 1];
                        MMA_F16(accs[nt], a2[0], a2[1], a2[2], a2[3], b0, b1);
                    }
                }
            }
            int row0 = (wid << 4) + er;
#pragma unroll
            for (int nt = 0; nt < 4; nt++) {
                int col = nt * 8 + ec;
                *(float2*)(dstS + (size_t)row0 * HH + col) =
                    make_float2(accs[nt][0], accs[nt][1]);
                *(float2*)(dstS + (size_t)(row0 + 8) * HH + col) =
                    make_float2(accs[nt][2], accs[nt][3]);
            }
        }

        gsync(++bt);

        // ---- LN + tanh: 2 rows per CTA per batch, 3 batches ----
#pragma unroll 1
        for (int it = 0; it < 3; it++) {
            const int base = it * 296 + (blockIdx.x << 1);
            if (base >= 768) break;
            const int row = base + rhalf;
            const int task = row >> 7, b = row & 127;
            const int dd = task / 3, ll = task - dd * 3;
            const int tt2 = s - ll;
            const bool rvalid = (tt2 >= 0 && tt2 < TT);

            float4 v = make_float4(0.f, 0.f, 0.f, 0.f);
            if (rvalid) {
                const float* ppb = g_pp + (size_t)(dd * 3 + ll) * 8 * (BB * HH)
                                        + (size_t)b * HH + lj;
                float4 cb = *(const float4*)(g_cb + task * HH + lj);
                if (ll == 0) {
                    float4 x0 = *(const float4*)(g_X0 + ((size_t)(dd * TT + tt2) * BB + b) * HH + lj);
                    float4 p[4];
#pragma unroll
                    for (int c = 0; c < 4; c++)
                        p[c] = *(const float4*)(ppb + (size_t)c * (BB * HH));
                    v.x = cb.x + x0.x + p[0].x + p[1].x + p[2].x + p[3].x;
                    v.y = cb.y + x0.y + p[0].y + p[1].y + p[2].y + p[3].y;
                    v.z = cb.z + x0.z + p[0].z + p[1].z + p[2].z + p[3].z;
                    v.w = cb.w + x0.w + p[0].w + p[1].w + p[2].w + p[3].w;
                } else {
                    float4 p[8];
#pragma unroll
                    for (int c = 0; c < 8; c++)
                        p[c] = *(const float4*)(ppb + (size_t)c * (BB * HH));
                    v.x = cb.x + p[0].x + p[1].x + p[2].x + p[3].x + p[4].x + p[5].x + p[6].x + p[7].x;
                    v.y = cb.y + p[0].y + p[1].y + p[2].y + p[3].y + p[4].y + p[5].y + p[6].y + p[7].y;
                    v.z = cb.z + p[0].z + p[1].z + p[2].z + p[3].z + p[4].z + p[5].z + p[6].z + p[7].z;
                    v.w = cb.w + p[0].w + p[1].w + p[2].w + p[3].w + p[4].w + p[5].w + p[6].w + p[7].w;
                }
            }
            float s1 = v.x + v.y + v.z + v.w;
            float s2 = v.x * v.x + v.y * v.y + v.z * v.z + v.w * v.w;
#pragma unroll
            for (int o = 16; o > 0; o >>= 1) {
                s1 += __shfl_xor_sync(0xffffffffu, s1, o);
                s2 += __shfl_xor_sync(0xffffffffu, s2, o);
            }
            if (lane == 0) { redp[rhalf][0][lnwarp] = s1; redp[rhalf][1][lnwarp] = s2; }
            __syncthreads();
            if (rvalid) {
                float t1 = redp[rhalf][0][0] + redp[rhalf][0][1] + redp[rhalf][0][2] + redp[rhalf][0][3];
                float t2 = redp[rhalf][1][0] + redp[rhalf][1][1] + redp[rhalf][1][2] + redp[rhalf][1][3];
                const float mean = t1 * (1.f / HH);
                const float var  = t2 * (1.f / HH) - mean * mean;
                const float inv  = rsqrtf(var + LNEPS);
                float4 g4 = *(const float4*)(ln_g + ll * HH + lj);
                float4 b4 = *(const float4*)(ln_b + ll * HH + lj);
                float h0 = tanhf((v.x - mean) * inv * g4.x + b4.x);
                float h1 = tanhf((v.y - mean) * inv * g4.y + b4.y);
                float h2 = tanhf((v.z - mean) * inv * g4.z + b4.z);
                float h3 = tanhf((v.w - mean) * inv * g4.w + b4.w);
                size_t hidx = (size_t)(dd * 3 + ll) * BB * HH + (size_t)b * HH + lj;
                __half2 p01 = __floats2half2_rn(h0, h1);
                __half2 p23 = __floats2half2_rn(h2, h3);
                uint2 uh;
                uh.x = *(uint32_t*)&p01;
                uh.y = *(uint32_t*)&p23;
                *(uint2*)(g_hh + hidx) = uh;
                if (ll == 2)
                    *(float4*)(g_o2 + ((size_t)(dd * TT + tt2) * BB + b) * HH + lj) =
                        make_float4(h0, h1, h2, h3);
            }
            __syncthreads();
        }

        gsync(++bt);
    }
}

// ---------- X0 = Xh@(W0h+W0l) + Xl@W0h + b0   (fp16 3-product HMMA) ----------
__global__ void __launch_bounds__(256, 1) x0mma_kernel() {
    extern __shared__ char smem_raw[];
    const uint32_t sbase = smem_u32(smem_raw);
    const int tid = threadIdx.x;
    const int wid = tid >> 5, lane = tid & 31;
    const int wm = wid & 3, wn = wid >> 2;
    const int d = blockIdx.z;
    const int m0 = blockIdx.y * 128;
    const int n0 = blockIdx.x * 128;

    const __half* Ah = g_Xh + ((size_t)d * 32768 + m0) * 320;
    const __half* Al = g_Xl + ((size_t)d * 32768 + m0) * 320;
    const __half* Bh = g_W0h + ((size_t)d * HH + n0) * 320;
    const __half* Bl = g_W0l + ((size_t)d * HH + n0) * 320;

    // lane components for 128B-row tiles
    int aoff[2], aswz[2];
#pragma unroll
    for (int mt = 0; mt < 2; mt++) {
        int r = wm * 32 + mt * 16 + (lane & 15);
        aoff[mt] = r * 128;
        aswz[mt] = r & 7;
    }
    const int ahi = lane >> 4;
    int boff[4], bswz[4];
#pragma unroll
    for (int np = 0; np < 4; np++) {
        int nl = wn * 64 + np * 16 + (lane & 7) + ((lane >> 4) << 3);
        boff[np] = nl * 128;
        bswz[np] = nl & 7;
    }
    const int bhi = (lane >> 3) & 1;

    float acc[2][8][4];
#pragma unroll
    for (int mt = 0; mt < 2; mt++)
#pragma unroll
        for (int nt = 0; nt < 8; nt++)
#pragma unroll
            for (int i = 0; i < 4; i++) acc[mt][nt][i] = 0.f;

    for (int kc = 0; kc < 5; kc++) {
        __syncthreads();
        load_t64(sbase + X0_AH, Ah + kc * 64);
        load_t64(sbase + X0_AL, Al + kc * 64);
        load_t64(sbase + X0_BH, Bh + kc * 64);
        load_t64(sbase + X0_BL, Bl + kc * 64);
        __syncthreads();
#pragma unroll
        for (int ks = 0; ks < 4; ks++) {
            uint32_t ah[2][4], al[2][4];
#pragma unroll
            for (int mt = 0; mt < 2; mt++) {
                uint32_t sw = (uint32_t)((ks * 2 + ahi) ^ aswz[mt]) << 4;
                LDSM4(ah[mt][0], ah[mt][1], ah[mt][2], ah[mt][3], sbase + X0_AH + aoff[mt] + sw);
                LDSM4(al[mt][0], al[mt][1], al[mt][2], al[mt][3], sbase + X0_AL + aoff[mt] + sw);
            }
            uint32_t bh[4][4], bl[4][4];
#pragma unroll
            for (int np = 0; np < 4; np++) {
                uint32_t sw = (uint32_t)((ks * 2 + bhi) ^ bswz[np]) << 4;
                LDSM4(bh[np][0], bh[np][1], bh[np][2], bh[np][3], sbase + X0_BH + boff[np] + sw);
                LDSM4(bl[np][0], bl[np][1], bl[np][2], bl[np][3], sbase + X0_BL + boff[np] + sw);
            }
#pragma unroll
            for (int mt = 0; mt < 2; mt++)
#pragma unroll
                for (int nt = 0; nt < 8; nt++) {
                    int q = nt >> 1;
                    int i0 = (nt & 1) ? 2 : 0, i1 = (nt & 1) ? 3 : 1;
                    MMA_F16(acc[mt][nt], ah[mt][0], ah[mt][1], ah[mt][2], ah[mt][3],
                            bh[q][i0], bh[q][i1]);
                    MMA_F16(acc[mt][nt], ah[mt][0], ah[mt][1], ah[mt][2], ah[mt][3],
                            bl[q][i0], bl[q][i1]);
                    MMA_F16(acc[mt][nt], al[mt][0], al[mt][1], al[mt][2], al[mt][3],
                            bh[q][i0], bh[q][i1]);
                }
        }
    }

    const int er = lane >> 2, ec = (lane & 3) * 2;
    const int b = m0 >> 8;
    const int tb = m0 & 255;
#pragma unroll
    for (int mt = 0; mt < 2; mt++) {
#pragma unroll
        for (int nt = 0; nt < 8; nt++) {
            int col = n0 + wn * 64 + nt * 8 + ec;
            float b0a = g_b0[d * HH + col];
            float b0b = g_b0[d * HH + col + 1];
#pragma unroll
            for (int rr = 0; rr < 2; rr++) {
                int rowin = wm * 32 + mt * 16 + er + rr * 8;
                int t = tb + rowin;
                float* dst = g_X0 + ((size_t)(d * TT + t) * BB + b) * HH + col;
                *(float2*)dst = make_float2(acc[mt][nt][rr * 2 + 0] + b0a,
                                            acc[mt][nt][rr * 2 + 1] + b0b);
            }
        }
    }
}

// ---------- gather + concat + FC ----------
__global__ void final_kernel(const int* __restrict__ pad,
                             const float* __restrict__ W_fc, const float* __restrict__ b_fc,
                             float* __restrict__ out) {
    __shared__ float cs[4][1024];
    const int sub  = threadIdx.x >> 6;
    const int lane = threadIdx.x & 63;
    const int r = blockIdx.x * 4 + sub;
    const int b = r >> 8;
    const int t = r & 255;
    const int p = pad[b];
    const int tt = (t < p) ? (p - t - 1) : t;
    const float* a0 = g_o2 + ((size_t)(0 * TT + t)  * BB + b) * HH;
    const float* a1 = g_o2 + ((size_t)(1 * TT + tt) * BB + b) * HH;
#pragma unroll
    for (int i = 0; i < 4; i++) {
        int j = lane * 4 + i * 256;
        float4 vv = (j < 512) ? *(const float4*)(a0 + j) : *(const float4*)(a1 + j - 512);
        *(float4*)(&cs[sub][j]) = vv;
    }
    __syncthreads();
    if (lane < NCLS) {
        float acc = b_fc[lane];
#pragma unroll 8
        for (int k = 0; k < 1024; k++) acc = fmaf(cs[sub][k], W_fc[k * NCLS + lane], acc);
        out[(size_t)r * NCLS + lane] = acc;
    }
}

// ---------- host launcher ----------
extern "C" void kernel_launch(void* const* d_in, const int* in_sizes, int n_in,
                              void* d_out, int out_size) {
    (void)in_sizes; (void)n_in; (void)out_size;
    const float* x      = (const float*)d_in[0];
    const float* rx     = (const float*)d_in[1];
    const int*   pad    = (const int*)  d_in[2];
    const float* W_emb  = (const float*)d_in[4];
    const float* b_emb  = (const float*)d_in[5];
    const float* Wx_l2r = (const float*)d_in[6];
    const float* bx_l2r = (const float*)d_in[7];
    const float* Wh_l2r = (const float*)d_in[8];
    const float* bh_l2r = (const float*)d_in[9];
    const float* Wx_r2l = (const float*)d_in[10];
    const float* bx_r2l = (const float*)d_in[11];
    const float* Wh_r2l = (const float*)d_in[12];
    const float* bh_r2l = (const float*)d_in[13];
    const float* ln_g   = (const float*)d_in[14];
    const float* ln_b   = (const float*)d_in[15];
    const float* W_fc   = (const float*)d_in[16];
    const float* b_fc   = (const float*)d_in[17];
    float* out = (float*)d_out;

    static int attr_done = 0;
    if (!attr_done) {
        cudaFuncSetAttribute(persist_kernel, cudaFuncAttributeMaxDynamicSharedMemorySize, DSMEM);
        cudaFuncSetAttribute(x0mma_kernel, cudaFuncAttributeMaxDynamicSharedMemorySize, X0_DS);
        attr_done = 1;
    }

    init_kernel<<<(2 * 3 * BB * HH + 255) / 256, 256>>>(bx_l2r, bh_l2r, bx_r2l, bh_r2l);
    w0_kernel<<<dim3(8, 3, 2), 256>>>(W_emb, b_emb, Wx_l2r, bx_l2r, Wx_r2l, bx_r2l);
    w0conv_kernel<<<dim3(16, 10, 2), dim3(32, 8)>>>();
    xconv_kernel<<<2 * 32768, 320>>>(x, rx);
    convw_kernel<<<dim3(16, 16, 10), dim3(32, 8)>>>(Wx_l2r, Wh_l2r, Wx_r2l, Wh_r2l);
    x0mma_kernel<<<dim3(4, 256, 2), 256, X0_DS>>>();

    persist_kernel<<<GRID_P, 256, DSMEM>>>(ln_g, ln_b);

    final_kernel<<<8192, 256>>>(pad, W_fc, b_fc, out);
}

// round 8
// speedup vs baseline: 1.9499x; 1.0088x over previous
#include <cuda_runtime.h>
#include <cuda_fp16.h>
#include <math.h>
#include <stdint.h>

#define BB    128
#define TT    256
#define INDIM 300
#define HH    512
#define NCLS  45
#define LNEPS 1e-5f

#define GRID_P  148
#define NSTEPS  258

// persist smem layout (byte offsets)
#define SM_BH   0
#define SM_BL   32768
#define SM_A    65536
#define SM_SBH  98304
#define SM_SBL  102400
#define SM_A2   106496
#define DSMEM   139264

// x0mma smem layout
#define X0_AH  0
#define X0_AL  16384
#define X0_BH  32768
#define X0_BL  49152
#define X0_DS  65536

// ---------- device scratch ----------
__device__ float g_W0[2 * INDIM * HH];
__device__ float g_b0[2 * HH];
__device__ __align__(16) __half g_W0h[2 * HH * 320];        // [d][n][k320]
__device__ __align__(16) __half g_W0l[2 * HH * 320];
__device__ __align__(16) __half g_Xh[2 * 32768 * 320];      // [d][m][k320]
__device__ __align__(16) __half g_Xl[2 * 32768 * 320];
__device__ float g_X0[2 * TT * BB * HH];
__device__ __align__(16) __half g_Bh[10 * HH * HH];         // [mat][n][k512] hi
__device__ __align__(16) __half g_Bl[10 * HH * HH];         // lo
__device__ __align__(16) __half g_hh[2 * 3 * BB * HH];      // h fp16
__device__ float g_pp[2 * 3 * 8 * BB * HH];                 // slots (d*3+l)*8+kc
__device__ float g_o2[2 * TT * BB * HH];
__device__ float g_cb[6 * HH];
__device__ unsigned g_barc;
__device__ unsigned g_sense;

// ---------- helpers ----------
__device__ __forceinline__ uint32_t smem_u32(const void* p) {
    uint32_t a;
    asm("{ .reg .u64 t; cvta.to.shared.u64 t, %1; cvt.u32.u64 %0, t; }" : "=r"(a) : "l"(p));
    return a;
}

__device__ __forceinline__ void gsync(unsigned target) {
    __syncthreads();
    if (threadIdx.x == 0) {
        unsigned old;
        asm volatile("atom.add.acq_rel.gpu.u32 %0, [%1], 1;" : "=r"(old) : "l"(&g_barc) : "memory");
        if (old == (unsigned)(GRID_P - 1)) {
            asm volatile("st.relaxed.gpu.u32 [%0], 0;" :: "l"(&g_barc) : "memory");
            asm volatile("st.release.gpu.u32 [%0], %1;" :: "l"(&g_sense), "r"(target) : "memory");
        } else {
            unsigned sv;
            do {
                asm volatile("ld.acquire.gpu.u32 %0, [%1];" : "=r"(sv) : "l"(&g_sense) : "memory");
            } while (sv != target);
        }
        __threadfence();
    }
    __syncthreads();
}

// ---------- init ----------
__global__ void init_kernel(const float* __restrict__ bx_l2r, const float* __restrict__ bh_l2r,
                            const float* __restrict__ bx_r2l, const float* __restrict__ bh_r2l) {
    int i = blockIdx.x * blockDim.x + threadIdx.x;
    if (i == 0) { g_barc = 0; g_sense = 0; }
    if (i < 2 * 3 * BB * HH) g_hh[i] = __float2half(0.f);
    if (i < 6 * HH) {
        int task = i / HH, j = i % HH;
        int dd = task / 3, ll = task - dd * 3;
        const float* bx = dd ? bx_r2l : bx_l2r;
        const float* bh = dd ? bh_r2l : bh_l2r;
        float cb = bh[ll * HH + j];
        if (ll != 0) cb += bx[ll * HH + j];
        g_cb[i] = cb;
    }
}

// ---------- W0 = [W_emb; b_emb] @ Wx0 (+bx0), fp32 ----------
__global__ void w0_kernel(const float* __restrict__ W_emb, const float* __restrict__ b_emb,
                          const float* __restrict__ Wx_l2r, const float* __restrict__ bx_l2r,
                          const float* __restrict__ Wx_r2l, const float* __restrict__ bx_r2l) {
    const int d = blockIdx.z;
    const float* Wx0 = d ? Wx_r2l : Wx_l2r;
    const float* bx0 = d ? bx_r2l : bx_l2r;
    const int n0 = blockIdx.x * 64;
    const int m0 = blockIdx.y * 128;
    __shared__ float As[16][136];
    __shared__ float Bs[16][64];
    const int tid = threadIdx.x;
    const int ty = tid >> 4, tx = tid & 15;
    float acc[8][4];
#pragma unroll
    for (int i = 0; i < 8; i++)
#pragma unroll
        for (int j = 0; j < 4; j++) acc[i][j] = 0.f;

    for (int k0 = 0; k0 < HH; k0 += 16) {
        {
            const int row = tid >> 2, c4 = (tid & 3) * 4;
#pragma unroll
            for (int rr = 0; rr < 2; rr++) {
                int r = row + rr * 64;
                int gm = m0 + r;
                float4 av = make_float4(0.f, 0.f, 0.f, 0.f);
                if (gm < INDIM)       av = *(const float4*)(W_emb + (size_t)gm * HH + k0 + c4);
                else if (gm == INDIM) av = *(const float4*)(b_emb + k0 + c4);
                As[c4 + 0][r] = av.x; As[c4 + 1][r] = av.y;
                As[c4 + 2][r] = av.z; As[c4 + 3][r] = av.w;
            }
        }
        {
            const int row = tid >> 4, c4 = (tid & 15) * 4;
            float4 bv = *(const float4*)(Wx0 + (size_t)(k0 + row) * HH + n0 + c4);
            *(float4*)(&Bs[row][c4]) = bv;
        }
        __syncthreads();
#pragma unroll
        for (int kk = 0; kk < 16; kk++) {
            float4 a0 = *(const float4*)(&As[kk][ty * 8]);
            float4 a1 = *(const float4*)(&As[kk][ty * 8 + 4]);
            float4 b4 = *(const float4*)(&Bs[kk][tx * 4]);
            float a[8] = {a0.x, a0.y, a0.z, a0.w, a1.x, a1.y, a1.z, a1.w};
            float b[4] = {b4.x, b4.y, b4.z, b4.w};
#pragma unroll
            for (int i = 0; i < 8; i++)
#pragma unroll
                for (int j = 0; j < 4; j++) acc[i][j] = fmaf(a[i], b[j], acc[i][j]);
        }
        __syncthreads();
    }
#pragma unroll
    for (int i = 0; i < 8; i++) {
        int gm = m0 + ty * 8 + i;
        int gn = n0 + tx * 4;
        if (gm < INDIM) {
#pragma unroll
            for (int j = 0; j < 4; j++) g_W0[(size_t)(d * INDIM + gm) * HH + gn + j] = acc[i][j];
        } else if (gm == INDIM) {
#pragma unroll
            for (int j = 0; j < 4; j++) g_b0[d * HH + gn + j] = acc[i][j] + bx0[gn + j];
        }
    }
}

// ---------- W0 fp32 [d][k300][n] -> fp16 hi/lo transposed [d][n][k320] ----------
__global__ void w0conv_kernel() {
    __shared__ float tile[32][33];
    const int d = blockIdx.z;
    const int k0 = blockIdx.y * 32, n0 = blockIdx.x * 32;
    const int tx = threadIdx.x;
    for (int r = threadIdx.y; r < 32; r += 8) {
        int k = k0 + r;
        tile[r][tx] = (k < INDIM) ? g_W0[(size_t)(d * INDIM + k) * HH + n0 + tx] : 0.f;
    }
    __syncthreads();
    for (int r = threadIdx.y; r < 32; r += 8) {
        float v = tile[tx][r];
        __half hi = __float2half(v);
        __half lo = __float2half(v - __half2float(hi));
        size_t dst = ((size_t)d * HH + n0 + r) * 320 + k0 + tx;
        g_W0h[dst] = hi;
        g_W0l[dst] = lo;
    }
}

// ---------- x/rx -> fp16 hi/lo, K padded to 320 (vectorized) ----------
__global__ void xconv_kernel(const float* __restrict__ x, const float* __restrict__ rx) {
    const int tid = threadIdx.x;
    const int row = blockIdx.x * 16 + (tid >> 4);    // 0..65535
    const int d = row >> 15;
    const int m = row & 32767;
    const float* src = d ? rx : x;
    const float2* s2 = (const float2*)(src + (size_t)m * INDIM);
    __half2* dh = (__half2*)g_Xh + (size_t)row * 160;
    __half2* dl = (__half2*)g_Xl + (size_t)row * 160;
#pragma unroll
    for (int k = 0; k < 10; k++) {
        int c2 = (tid & 15) + 16 * k;
        float2 v = (c2 < 150) ? s2[c2] : make_float2(0.f, 0.f);
        __half hx = __float2half(v.x), hy = __float2half(v.y);
        __half lx = __float2half(v.x - __half2float(hx));
        __half ly = __float2half(v.y - __half2float(hy));
        dh[c2] = __halves2half2(hx, hy);
        dl[c2] = __halves2half2(lx, ly);
    }
}

// ---------- weights -> transposed fp16 hi/lo. mats/dir: 0=Wh0,1=Wx1,2=Wh1,3=Wx2,4=Wh2 ----------
__global__ void convw_kernel(const float* __restrict__ Wx_l2r, const float* __restrict__ Wh_l2r,
                             const float* __restrict__ Wx_r2l, const float* __restrict__ Wh_r2l) {
    const int mat = blockIdx.z;
    const int d = mat / 5, mm = mat % 5;
    const float* Wx = d ? Wx_r2l : Wx_l2r;
    const float* Wh = d ? Wh_r2l : Wh_l2r;
    const float* W;
    if      (mm == 0) W = Wh;
    else if (mm == 1) W = Wx + (size_t)1 * HH * HH;
    else if (mm == 2) W = Wh + (size_t)1 * HH * HH;
    else if (mm == 3) W = Wx + (size_t)2 * HH * HH;
    else              W = Wh + (size_t)2 * HH * HH;

    __shared__ float tile[32][33];
    const int k0 = blockIdx.y * 32, n0 = blockIdx.x * 32;
    for (int r = threadIdx.y; r < 32; r += 8)
        tile[r][threadIdx.x] = W[(size_t)(k0 + r) * HH + n0 + threadIdx.x];
    __syncthreads();
    for (int r = threadIdx.y; r < 32; r += 8) {
        float v = tile[threadIdx.x][r];
        __half hi = __float2half(v);
        __half lo = __float2half(v - __half2float(hi));
        size_t dst = ((size_t)mat * HH + n0 + r) * HH + k0 + threadIdx.x;
        g_Bh[dst] = hi;
        g_Bl[dst] = lo;
    }
}

// ---------- smem tile loaders (16B-chunk XOR swizzle) ----------
__device__ __forceinline__ void load_t128(uint32_t dst, const __half* __restrict__ src) {
    const int tid = threadIdx.x;
#pragma unroll
    for (int it = 0; it < 8; it++) {
        int idx = it * 256 + tid;
        int r = idx >> 4, c = idx & 15;
        uint4 v = *(const uint4*)(src + (size_t)r * 512 + c * 8);
        uint32_t a = dst + r * 256 + (((uint32_t)(c ^ (r & 7))) << 4);
        asm volatile("st.shared.v4.b32 [%0], {%1,%2,%3,%4};"
                     :: "r"(a), "r"(v.x), "r"(v.y), "r"(v.z), "r"(v.w) : "memory");
    }
}
// 16 rows x 128 halfs
__device__ __forceinline__ void load_t16(uint32_t dst, const __half* __restrict__ src) {
    const int tid = threadIdx.x;
    int r = tid >> 4, c = tid & 15;
    uint4 v = *(const uint4*)(src + (size_t)r * 512 + c * 8);
    uint32_t a = dst + r * 256 + (((uint32_t)(c ^ (r & 7))) << 4);
    asm volatile("st.shared.v4.b32 [%0], {%1,%2,%3,%4};"
                 :: "r"(a), "r"(v.x), "r"(v.y), "r"(v.z), "r"(v.w) : "memory");
}
// 128 rows x 64 halfs, src row stride 320 halfs
__device__ __forceinline__ void load_t64(uint32_t dst, const __half* __restrict__ src) {
    const int tid = threadIdx.x;
#pragma unroll
    for (int it = 0; it < 4; it++) {
        int idx = it * 256 + tid;
        int r = idx >> 3, c = idx & 7;
        uint4 v = *(const uint4*)(src + (size_t)r * 320 + c * 8);
        uint32_t a = dst + r * 128 + (((uint32_t)(c ^ (r & 7))) << 4);
        asm volatile("st.shared.v4.b32 [%0], {%1,%2,%3,%4};"
                     :: "r"(a), "r"(v.x), "r"(v.y), "r"(v.z), "r"(v.w) : "memory");
    }
}

#define MMA_F16(acc, a0, a1, a2, a3, b0, b1) \
    asm volatile( \
        "mma.sync.aligned.m16n8k16.row.col.f32.f16.f16.f32 " \
        "{%0,%1,%2,%3}, {%4,%5,%6,%7}, {%8,%9}, {%0,%1,%2,%3};" \
        : "+f"((acc)[0]), "+f"((acc)[1]), "+f"((acc)[2]), "+f"((acc)[3]) \
        : "r"(a0), "r"(a1), "r"(a2), "r"(a3), "r"(b0), "r"(b1))

#define LDSM4(r0, r1, r2, r3, addr) \
    asm volatile("ldmatrix.sync.aligned.m8n8.x4.shared.b16 {%0,%1,%2,%3}, [%4];" \
                 : "=r"(r0), "=r"(r1), "=r"(r2), "=r"(r3) : "r"(addr))

// ---------- main fused GEMM: acc = A(128x128) @ (Bh+Bl)(128n x 128k)^T ----------
__device__ __forceinline__ void gemm_main(uint32_t smA, uint32_t smBh, uint32_t smBl,
                                          const int aoff[2], const int aswz[2], int ahi,
                                          const int boff[4], const int bswz[4], int bhi,
                                          float acc[2][8][4]) {
#pragma unroll
    for (int mt = 0; mt < 2; mt++)
#pragma unroll
        for (int nt = 0; nt < 8; nt++)
#pragma unroll
            for (int i = 0; i < 4; i++) acc[mt][nt][i] = 0.f;
#pragma unroll 2
    for (int ks = 0; ks < 8; ks++) {
        uint32_t a[2][4];
#pragma unroll
        for (int mt = 0; mt < 2; mt++) {
            uint32_t addr = smA + aoff[mt] + ((uint32_t)((ks * 2 + ahi) ^ aswz[mt]) << 4);
            LDSM4(a[mt][0], a[mt][1], a[mt][2], a[mt][3], addr);
        }
#pragma unroll
        for (int half = 0; half < 2; half++) {
            uint32_t smB = half ? smBl : smBh;
            uint32_t bq[4][4];
#pragma unroll
            for (int np = 0; np < 4; np++) {
                uint32_t addr = smB + boff[np] + ((uint32_t)((ks * 2 + bhi) ^ bswz[np]) << 4);
                LDSM4(bq[np][0], bq[np][1], bq[np][2], bq[np][3], addr);
            }
#pragma unroll
            for (int mt = 0; mt < 2; mt++)
#pragma unroll
                for (int nt = 0; nt < 8; nt++) {
                    uint32_t b0 = bq[nt >> 1][(nt & 1) ? 2 : 0];
                    uint32_t b1 = bq[nt >> 1][(nt & 1) ? 3 : 1];
                    MMA_F16(acc[mt][nt], a[mt][0], a[mt][1], a[mt][2], a[mt][3], b0, b1);
                }
        }
    }
}

// ---------- persistent wavefront kernel ----------
__global__ void __launch_bounds__(256, 1)
persist_kernel(const float* __restrict__ ln_g, const float* __restrict__ ln_b) {
    extern __shared__ char smem_raw[];
    const uint32_t sbase = smem_u32(smem_raw);
    const int tid = threadIdx.x;
    const int wid = tid >> 5, lane = tid & 31;
    const int wm = wid & 3, wn = wid >> 2;

    int aoff[2], aswz[2];
#pragma unroll
    for (int mt = 0; mt < 2; mt++) {
        int r = wm * 32 + mt * 16 + (lane & 15);
        aoff[mt] = r * 256;
        aswz[mt] = r & 7;
    }
    const int ahi = lane >> 4;
    int boff[4], bswz[4];
#pragma unroll
    for (int np = 0; np < 4; np++) {
        int nl = wn * 64 + np * 16 + (lane & 7) + ((lane >> 4) << 3);
        boff[np] = nl * 256;
        bswz[np] = nl & 7;
    }
    const int bhi = (lane >> 3) & 1;

    auto decode = [](int u, int& d, int& l, int& ntile, int& kc, int& mat, int& asrc) {
        d = u / 80;
        int r = u % 80;
        if (r < 16)      { l = 0; ntile = r >> 2;        kc = r & 3;
                           mat = d * 5 + 0; asrc = 0; }
        else if (r < 48) { l = 1; int rr = r - 16; ntile = rr >> 3; kc = rr & 7;
                           if (kc < 4) { mat = d * 5 + 1; asrc = 0; }
                           else        { mat = d * 5 + 2; asrc = 1; } }
        else             { l = 2; int rr = r - 48; ntile = rr >> 3; kc = rr & 7;
                           if (kc < 4) { mat = d * 5 + 3; asrc = 1; }
                           else        { mat = d * 5 + 4; asrc = 2; } }
    };

    const int cta = blockIdx.x;
    // main unit (all 148 CTAs): units 0..147
    int dM, lM, ntM, kcM, matM, asM;
    decode(cta, dM, lM, ntM, kcM, matM, asM);
    const int koffM = (kcM & 3) * 128;
    const int n0M = ntM * 128;
    const __half* Amain = g_hh + (size_t)(dM * 3 + asM) * BB * HH + koffM;
    float* dstM = g_pp + (size_t)((dM * 3 + lM) * 8 + kcM) * (BB * HH) + n0M;
    load_t128(sbase + SM_BH, g_Bh + ((size_t)matM * HH + n0M) * HH + koffM);
    load_t128(sbase + SM_BL, g_Bl + ((size_t)matM * HH + n0M) * HH + koffM);

    // sub slices: units 148..159 split into 96 N=16 slices on CTAs 48..143
    const bool hasSub = (cta >= 48 && cta < 144);
    int lS = 0;
    const __half* Asub = nullptr;
    float* dstS = nullptr;
    if (hasSub) {
        int j = cta - 48;
        int su = 148 + (j >> 3);
        int nsub = j & 7;
        int dS, ntS, kcS, matS, asS;
        decode(su, dS, lS, ntS, kcS, matS, asS);
        int koffS = (kcS & 3) * 128;
        int n0S = ntS * 128 + nsub * 16;
        Asub = g_hh + (size_t)(dS * 3 + asS) * BB * HH + koffS;
        dstS = g_pp + (size_t)((dS * 3 + lS) * 8 + kcS) * (BB * HH) + n0S;
        load_t16(sbase + SM_SBH, g_Bh + ((size_t)matS * HH + n0S) * HH + koffS);
        load_t16(sbase + SM_SBL, g_Bl + ((size_t)matS * HH + n0S) * HH + koffS);
    }
    __syncthreads();

    const int er = lane >> 2, ec = (lane & 3) * 2;
    // sub-slice lane components
    const int ar2 = (wid << 4) + (lane & 15);
    const int aoff2 = ar2 * 256, aswz2 = ar2 & 7;
    const int nl2 = (lane & 7) + ((lane >> 4) << 3);
    const int boff2 = nl2 * 256, bswz2 = nl2 & 7;

    float acc[2][8][4];
    unsigned bt = 0;

    for (int s = 0; s < NSTEPS; s++) {
        const int tM = s - lM;
        const bool runM = (tM >= 0 && tM < TT);
        const int tS = s - lS;
        const bool runS = hasSub && (tS >= 0 && tS < TT);

        if (runM) load_t128(sbase + SM_A, Amain);
        if (runS) load_t128(sbase + SM_A2, Asub);
        __syncthreads();

        if (runM) {
            gemm_main(sbase + SM_A, sbase + SM_BH, sbase + SM_BL,
                      aoff, aswz, ahi, boff, bswz, bhi, acc);
#pragma unroll
            for (int mt = 0; mt < 2; mt++) {
                int row0 = wm * 32 + mt * 16 + er;
#pragma unroll
                for (int nt = 0; nt < 8; nt++) {
                    int col = wn * 64 + nt * 8 + ec;
                    *(float2*)(dstM + (size_t)row0 * HH + col) =
                        make_float2(acc[mt][nt][0], acc[mt][nt][1]);
                    *(float2*)(dstM + (size_t)(row0 + 8) * HH + col) =
                        make_float2(acc[mt][nt][2], acc[mt][nt][3]);
                }
            }
        }
        if (runS) {
            float accs[2][4];
#pragma unroll
            for (int nt = 0; nt < 2; nt++)
#pragma unroll
                for (int i = 0; i < 4; i++) accs[nt][i] = 0.f;
#pragma unroll 2
            for (int ks = 0; ks < 8; ks++) {
                uint32_t a2[4];
                uint32_t addr = sbase + SM_A2 + aoff2 + ((uint32_t)((ks * 2 + ahi) ^ aswz2) << 4);
                LDSM4(a2[0], a2[1], a2[2], a2[3], addr);
#pragma unroll
                for (int half = 0; half < 2; half++) {
                    uint32_t smB = sbase + (half ? SM_SBL : SM_SBH);
                    uint32_t bq[4];
                    uint32_t ba = smB + boff2 + ((uint32_t)((ks * 2 + bhi) ^ bswz2) << 4);
                    LDSM4(bq[0], bq[1], bq[2], bq[3], ba);
                    MMA_F16(accs[0], a2[0], a2[1], a2[2], a2[3], bq[0], bq[1]);
                    MMA_F16(accs[1], a2[0], a2[1], a2[2], a2[3], bq[2], bq[3]);
                }
            }
            int row0 = (wid << 4) + er;
#pragma unroll
            for (int nt = 0; nt < 2; nt++) {
                int col = nt * 8 + ec;
                *(float2*)(dstS + (size_t)row0 * HH + col) =
                    make_float2(accs[nt][0], accs[nt][1]);
                *(float2*)(dstS + (size_t)(row0 + 8) * HH + col) =
                    make_float2(accs[nt][2], accs[nt][3]);
            }
        }

        gsync(++bt);

        // ---- LN + tanh: warp-per-row, single pass (96 CTAs x 8 warps = 768 rows) ----
        if (cta < 96) {
            const int row = (cta << 3) + wid;
            const int task = row >> 7, b = row & 127;
            const int dd = (task >= 3) ? 1 : 0;
            const int ll = task - dd * 3;
            const int tt2 = s - ll;
            if (tt2 >= 0 && tt2 < TT) {
                const int j0 = lane << 4;
                const float* cbp = g_cb + task * HH + j0;
                const float* ppb = g_pp + (size_t)task * 8 * (BB * HH) + (size_t)b * HH + j0;
                float4 v0 = ((const float4*)cbp)[0];
                float4 v1 = ((const float4*)cbp)[1];
                float4 v2 = ((const float4*)cbp)[2];
                float4 v3 = ((const float4*)cbp)[3];
                if (ll == 0) {
                    const float* x0p = g_X0 + ((size_t)(dd * TT + tt2) * BB + b) * HH + j0;
                    {
                        float4 q0 = ((const float4*)x0p)[0], q1 = ((const float4*)x0p)[1];
                        float4 q2 = ((const float4*)x0p)[2], q3 = ((const float4*)x0p)[3];
                        v0.x += q0.x; v0.y += q0.y; v0.z += q0.z; v0.w += q0.w;
                        v1.x += q1.x; v1.y += q1.y; v1.z += q1.z; v1.w += q1.w;
                        v2.x += q2.x; v2.y += q2.y; v2.z += q2.z; v2.w += q2.w;
                        v3.x += q3.x; v3.y += q3.y; v3.z += q3.z; v3.w += q3.w;
                    }
#pragma unroll
                    for (int c = 0; c < 4; c++) {
                        const float4* p4 = (const float4*)(ppb + (size_t)c * (BB * HH));
                        float4 q0 = p4[0], q1 = p4[1], q2 = p4[2], q3 = p4[3];
                        v0.x += q0.x; v0.y += q0.y; v0.z += q0.z; v0.w += q0.w;
                        v1.x += q1.x; v1.y += q1.y; v1.z += q1.z; v1.w += q1.w;
                        v2.x += q2.x; v2.y += q2.y; v2.z += q2.z; v2.w += q2.w;
                        v3.x += q3.x; v3.y += q3.y; v3.z += q3.z; v3.w += q3.w;
                    }
                } else {
#pragma unroll
                    for (int c = 0; c < 8; c++) {
                        const float4* p4 = (const float4*)(ppb + (size_t)c * (BB * HH));
                        float4 q0 = p4[0], q1 = p4[1], q2 = p4[2], q3 = p4[3];
                        v0.x += q0.x; v0.y += q0.y; v0.z += q0.z; v0.w += q0.w;
                        v1.x += q1.x; v1.y += q1.y; v1.z += q1.z; v1.w += q1.w;
                        v2.x += q2.x; v2.y += q2.y; v2.z += q2.z; v2.w += q2.w;
                        v3.x += q3.x; v3.y += q3.y; v3.z += q3.z; v3.w += q3.w;
                    }
                }
                float s1 = (v0.x + v0.y + v0.z + v0.w) + (v1.x + v1.y + v1.z + v1.w)
                         + (v2.x + v2.y + v2.z + v2.w) + (v3.x + v3.y + v3.z + v3.w);
                float s2 = (v0.x * v0.x + v0.y * v0.y + v0.z * v0.z + v0.w * v0.w)
                         + (v1.x * v1.x + v1.y * v1.y + v1.z * v1.z + v1.w * v1.w)
                         + (v2.x * v2.x + v2.y * v2.y + v2.z * v2.z + v2.w * v2.w)
                         + (v3.x * v3.x + v3.y * v3.y + v3.z * v3.z + v3.w * v3.w);
#pragma unroll
                for (int o = 16; o > 0; o >>= 1) {
                    s1 += __shfl_xor_sync(0xffffffffu, s1, o);
                    s2 += __shfl_xor_sync(0xffffffffu, s2, o);
                }
                const float mean = s1 * (1.f / HH);
                const float var  = s2 * (1.f / HH) - mean * mean;
                const float inv  = rsqrtf(var + LNEPS);
                const float4* gg = (const float4*)(ln_g + ll * HH + j0);
                const float4* bb = (const float4*)(ln_b + ll * HH + j0);
                float hs[16];
#pragma unroll
                for (int q = 0; q < 4; q++) {
                    float4 vq = (q == 0) ? v0 : (q == 1) ? v1 : (q == 2) ? v2 : v3;
                    float4 g4 = gg[q], b4 = bb[q];
                    hs[q * 4 + 0] = tanhf((vq.x - mean) * inv * g4.x + b4.x);
                    hs[q * 4 + 1] = tanhf((vq.y - mean) * inv * g4.y + b4.y);
                    hs[q * 4 + 2] = tanhf((vq.z - mean) * inv * g4.z + b4.z);
                    hs[q * 4 + 3] = tanhf((vq.w - mean) * inv * g4.w + b4.w);
                }
                size_t hidx = (size_t)task * BB * HH + (size_t)b * HH + j0;
                uint4 u0, u1;
                {
                    __half2 p0 = __floats2half2_rn(hs[0], hs[1]);
                    __half2 p1 = __floats2half2_rn(hs[2], hs[3]);
                    __half2 p2 = __floats2half2_rn(hs[4], hs[5]);
                    __half2 p3 = __floats2half2_rn(hs[6], hs[7]);
                    u0.x = *(uint32_t*)&p0; u0.y = *(uint32_t*)&p1;
                    u0.z = *(uint32_t*)&p2; u0.w = *(uint32_t*)&p3;
                    __half2 p4 = __floats2half2_rn(hs[8], hs[9]);
                    __half2 p5 = __floats2half2_rn(hs[10], hs[11]);
                    __half2 p6 = __floats2half2_rn(hs[12], hs[13]);
                    __half2 p7 = __floats2half2_rn(hs[14], hs[15]);
                    u1.x = *(uint32_t*)&p4; u1.y = *(uint32_t*)&p5;
                    u1.z = *(uint32_t*)&p6; u1.w = *(uint32_t*)&p7;
                }
                ((uint4*)(g_hh + hidx))[0] = u0;
                ((uint4*)(g_hh + hidx))[1] = u1;
                if (ll == 2) {
                    float* o2p = g_o2 + ((size_t)(dd * TT + tt2) * BB + b) * HH + j0;
#pragma unroll
                    for (int q = 0; q < 4; q++)
                        ((float4*)o2p)[q] = make_float4(hs[q * 4 + 0], hs[q * 4 + 1],
                                                        hs[q * 4 + 2], hs[q * 4 + 3]);
                }
            }
        }

        gsync(++bt);
    }
}

// ---------- X0 = Xh@(W0h+W0l) + Xl@W0h + b0   (fp16 3-product HMMA) ----------
__global__ void __launch_bounds__(256, 1) x0mma_kernel() {
    extern __shared__ char smem_raw[];
    const uint32_t sbase = smem_u32(smem_raw);
    const int tid = threadIdx.x;
    const int wid = tid >> 5, lane = tid & 31;
    const int wm = wid & 3, wn = wid >> 2;
    const int d = blockIdx.z;
    const int m0 = blockIdx.y * 128;
    const int n0 = blockIdx.x * 128;

    const __half* Ah = g_Xh + ((size_t)d * 32768 + m0) * 320;
    const __half* Al = g_Xl + ((size_t)d * 32768 + m0) * 320;
    const __half* Bh = g_W0h + ((size_t)d * HH + n0) * 320;
    const __half* Bl = g_W0l + ((size_t)d * HH + n0) * 320;

    int aoff[2], aswz[2];
#pragma unroll
    for (int mt = 0; mt < 2; mt++) {
        int r = wm * 32 + mt * 16 + (lane & 15);
        aoff[mt] = r * 128;
        aswz[mt] = r & 7;
    }
    const int ahi = lane >> 4;
    int boff[4], bswz[4];
#pragma unroll
    for (int np = 0; np < 4; np++) {
        int nl = wn * 64 + np * 16 + (lane & 7) + ((lane >> 4) << 3);
        boff[np] = nl * 128;
        bswz[np] = nl & 7;
    }
    const int bhi = (lane >> 3) & 1;

    float acc[2][8][4];
#pragma unroll
    for (int mt = 0; mt < 2; mt++)
#pragma unroll
        for (int nt = 0; nt < 8; nt++)
#pragma unroll
            for (int i = 0; i < 4; i++) acc[mt][nt][i] = 0.f;

    for (int kc = 0; kc < 5; kc++) {
        __syncthreads();
        load_t64(sbase + X0_AH, Ah + kc * 64);
        load_t64(sbase + X0_AL, Al + kc * 64);
        load_t64(sbase + X0_BH, Bh + kc * 64);
        load_t64(sbase + X0_BL, Bl + kc * 64);
        __syncthreads();
#pragma unroll
        for (int ks = 0; ks < 4; ks++) {
            uint32_t ah[2][4], al[2][4];
#pragma unroll
            for (int mt = 0; mt < 2; mt++) {
                uint32_t sw = (uint32_t)((ks * 2 + ahi) ^ aswz[mt]) << 4;
                LDSM4(ah[mt][0], ah[mt][1], ah[mt][2], ah[mt][3], sbase + X0_AH + aoff[mt] + sw);
                LDSM4(al[mt][0], al[mt][1], al[mt][2], al[mt][3], sbase + X0_AL + aoff[mt] + sw);
            }
            uint32_t bh[4][4], bl[4][4];
#pragma unroll
            for (int np = 0; np < 4; np++) {
                uint32_t sw = (uint32_t)((ks * 2 + bhi) ^ bswz[np]) << 4;
                LDSM4(bh[np][0], bh[np][1], bh[np][2], bh[np][3], sbase + X0_BH + boff[np] + sw);
                LDSM4(bl[np][0], bl[np][1], bl[np][2], bl[np][3], sbase + X0_BL + boff[np] + sw);
            }
#pragma unroll
            for (int mt = 0; mt < 2; mt++)
#pragma unroll
                for (int nt = 0; nt < 8; nt++) {
                    int q = nt >> 1;
                    int i0 = (nt & 1) ? 2 : 0, i1 = (nt & 1) ? 3 : 1;
                    MMA_F16(acc[mt][nt], ah[mt][0], ah[mt][1], ah[mt][2], ah[mt][3],
                            bh[q][i0], bh[q][i1]);
                    MMA_F16(acc[mt][nt], ah[mt][0], ah[mt][1], ah[mt][2], ah[mt][3],
                            bl[q][i0], bl[q][i1]);
                    MMA_F16(acc[mt][nt], al[mt][0], al[mt][1], al[mt][2], al[mt][3],
                            bh[q][i0], bh[q][i1]);
                }
        }
    }

    const int er = lane >> 2, ec = (lane & 3) * 2;
    const int b = m0 >> 8;
    const int tb = m0 & 255;
#pragma unroll
    for (int mt = 0; mt < 2; mt++) {
#pragma unroll
        for (int nt = 0; nt < 8; nt++) {
            int col = n0 + wn * 64 + nt * 8 + ec;
            float b0a = g_b0[d * HH + col];
            float b0b = g_b0[d * HH + col + 1];
#pragma unroll
            for (int rr = 0; rr < 2; rr++) {
                int rowin = wm * 32 + mt * 16 + er + rr * 8;
                int t = tb + rowin;
                float* dst = g_X0 + ((size_t)(d * TT + t) * BB + b) * HH + col;
                *(float2*)dst = make_float2(acc[mt][nt][rr * 2 + 0] + b0a,
                                            acc[mt][nt][rr * 2 + 1] + b0b);
            }
        }
    }
}

// ---------- gather + concat + FC (8 rows/block to cut W_fc L2 traffic) ----------
__global__ void final_kernel(const int* __restrict__ pad,
                             const float* __restrict__ W_fc, const float* __restrict__ b_fc,
                             float* __restrict__ out) {
    __shared__ float cs[8][1024];
    const int sub  = threadIdx.x >> 6;
    const int lane = threadIdx.x & 63;
    const int r = blockIdx.x * 8 + sub;
    const int b = r >> 8;
    const int t = r & 255;
    const int p = pad[b];
    const int tt = (t < p) ? (p - t - 1) : t;
    const float* a0 = g_o2 + ((size_t)(0 * TT + t)  * BB + b) * HH;
    const float* a1 = g_o2 + ((size_t)(1 * TT + tt) * BB + b) * HH;
#pragma unroll
    for (int i = 0; i < 4; i++) {
        int j = lane * 4 + i * 256;
        float4 vv = (j < 512) ? *(const float4*)(a0 + j) : *(const float4*)(a1 + j - 512);
        *(float4*)(&cs[sub][j]) = vv;
    }
    __syncthreads();
    if (lane < NCLS) {
        float acc = b_fc[lane];
#pragma unroll 8
        for (int k = 0; k < 1024; k++) acc = fmaf(cs[sub][k], W_fc[k * NCLS + lane], acc);
        out[(size_t)r * NCLS + lane] = acc;
    }
}

// ---------- host launcher ----------
extern "C" void kernel_launch(void* const* d_in, const int* in_sizes, int n_in,
                              void* d_out, int out_size) {
    (void)in_sizes; (void)n_in; (void)out_size;
    const float* x      = (const float*)d_in[0];
    const float* rx     = (const float*)d_in[1];
    const int*   pad    = (const int*)  d_in[2];
    const float* W_emb  = (const float*)d_in[4];
    const float* b_emb  = (const float*)d_in[5];
    const float* Wx_l2r = (const float*)d_in[6];
    const float* bx_l2r = (const float*)d_in[7];
    const float* Wh_l2r = (const float*)d_in[8];
    const float* bh_l2r = (const float*)d_in[9];
    const float* Wx_r2l = (const float*)d_in[10];
    const float* bx_r2l = (const float*)d_in[11];
    const float* Wh_r2l = (const float*)d_in[12];
    const float* bh_r2l = (const float*)d_in[13];
    const float* ln_g   = (const float*)d_in[14];
    const float* ln_b   = (const float*)d_in[15];
    const float* W_fc   = (const float*)d_in[16];
    const float* b_fc   = (const float*)d_in[17];
    float* out = (float*)d_out;

    static int attr_done = 0;
    if (!attr_done) {
        cudaFuncSetAttribute(persist_kernel, cudaFuncAttributeMaxDynamicSharedMemorySize, DSMEM);
        cudaFuncSetAttribute(x0mma_kernel, cudaFuncAttributeMaxDynamicSharedMemorySize, X0_DS);
        attr_done = 1;
    }

    init_kernel<<<(2 * 3 * BB * HH + 255) / 256, 256>>>(bx_l2r, bh_l2r, bx_r2l, bh_r2l);
    w0_kernel<<<dim3(8, 3, 2), 256>>>(W_emb, b_emb, Wx_l2r, bx_l2r, Wx_r2l, bx_r2l);
    w0conv_kernel<<<dim3(16, 10, 2), dim3(32, 8)>>>();
    xconv_kernel<<<4096, 256>>>(x, rx);
    convw_kernel<<<dim3(16, 16, 10), dim3(32, 8)>>>(Wx_l2r, Wh_l2r, Wx_r2l, Wh_r2l);
    x0mma_kernel<<<dim3(4, 256, 2), 256, X0_DS>>>();

    persist_kernel<<<GRID_P, 256, DSMEM>>>(ln_g, ln_b);

    final_kernel<<<4096, 512>>>(pad, W_fc, b_fc, out);
}